// round 8
// baseline (speedup 1.0000x reference)
#include <cuda_runtime.h>
#include <cuda_bf16.h>
#include <cstdint>

// ---------------------------------------------------------------------------
// Problem constants
// ---------------------------------------------------------------------------
constexpr int HID_C = 2048;
constexpr int H_C   = 16;
constexpr int KV_C  = 2;
constexpr int D_C   = 128;
constexpr int MAXM  = 4096;
constexpr int NCAT  = HID_C + 2 * KV_C * D_C;   // 2560 fused QKV output cols

// ---------------------------------------------------------------------------
// Scratch (static __device__; no allocation anywhere)
// ---------------------------------------------------------------------------
__device__ float g_qkv[MAXM * NCAT];             // fused QKV projection output
__device__ float g_bcat[NCAT];                   // concat bias

__device__ __nv_bfloat16 g_xh[MAXM * HID_C],  g_xl[MAXM * HID_C];
__device__ __nv_bfloat16 g_wcath[NCAT * HID_C], g_wcatl[NCAT * HID_C];
__device__ __nv_bfloat16 g_woh[HID_C * HID_C], g_wol[HID_C * HID_C];
__device__ __nv_bfloat16 g_ah[MAXM * HID_C],  g_al[MAXM * HID_C];

__device__ __nv_bfloat16 g_qh[MAXM * HID_C],       g_ql[MAXM * HID_C];
__device__ __nv_bfloat16 g_kh[MAXM * KV_C * D_C],  g_kl[MAXM * KV_C * D_C];
__device__ __nv_bfloat16 g_vh[MAXM * KV_C * D_C],  g_vl[MAXM * KV_C * D_C];

// ---------------------------------------------------------------------------
// Helpers
// ---------------------------------------------------------------------------
__device__ __forceinline__ uint32_t smem_u32(const void* p) {
  return (uint32_t)__cvta_generic_to_shared(p);
}
__device__ __forceinline__ void cp_async16(uint32_t dst, const void* src) {
  asm volatile("cp.async.cg.shared.global [%0], [%1], 16;" :: "r"(dst), "l"(src));
}
__device__ __forceinline__ void cp_commit() { asm volatile("cp.async.commit_group;"); }
__device__ __forceinline__ void cp_wait1()  { asm volatile("cp.async.wait_group 1;"); }
__device__ __forceinline__ void cp_wait0()  { asm volatile("cp.async.wait_group 0;"); }

__device__ __forceinline__ void ldmx4(uint32_t (&r)[4], uint32_t addr) {
  asm volatile("ldmatrix.sync.aligned.m8n8.x4.shared.b16 {%0,%1,%2,%3}, [%4];"
               : "=r"(r[0]), "=r"(r[1]), "=r"(r[2]), "=r"(r[3]) : "r"(addr));
}
__device__ __forceinline__ void ldmx4t(uint32_t (&r)[4], uint32_t addr) {
  asm volatile("ldmatrix.sync.aligned.m8n8.x4.trans.shared.b16 {%0,%1,%2,%3}, [%4];"
               : "=r"(r[0]), "=r"(r[1]), "=r"(r[2]), "=r"(r[3]) : "r"(addr));
}
__device__ __forceinline__ void mma_bf16(float (&d)[4], const uint32_t (&a)[4],
                                         const uint32_t b0, const uint32_t b1) {
  asm volatile(
      "mma.sync.aligned.m16n8k16.row.col.f32.bf16.bf16.f32 "
      "{%0,%1,%2,%3}, {%4,%5,%6,%7}, {%8,%9}, {%0,%1,%2,%3};"
      : "+f"(d[0]), "+f"(d[1]), "+f"(d[2]), "+f"(d[3])
      : "r"(a[0]), "r"(a[1]), "r"(a[2]), "r"(a[3]), "r"(b0), "r"(b1));
}

// ---------------------------------------------------------------------------
// Small kernels: bias concat, fp32 -> bf16 hi/lo split (plain + strided)
// ---------------------------------------------------------------------------
__global__ void bias_concat(const float* __restrict__ bq, const float* __restrict__ bk,
                            const float* __restrict__ bv, float* __restrict__ bc) {
  int i = blockIdx.x * blockDim.x + threadIdx.x;
  if (i >= NCAT) return;
  float v;
  if (i < HID_C) v = bq[i];
  else if (i < HID_C + KV_C * D_C) v = bk[i - HID_C];
  else v = bv[i - HID_C - KV_C * D_C];
  bc[i] = v;
}

__global__ void split_kernel(const float* __restrict__ s, __nv_bfloat16* __restrict__ hi,
                             __nv_bfloat16* __restrict__ lo, int n4) {
  int i = blockIdx.x * blockDim.x + threadIdx.x;
  if (i >= n4) return;
  float4 v = ((const float4*)s)[i];
  __nv_bfloat16 h[4], l[4];
  float f[4] = {v.x, v.y, v.z, v.w};
#pragma unroll
  for (int j = 0; j < 4; ++j) {
    h[j] = __float2bfloat16(f[j]);
    l[j] = __float2bfloat16(f[j] - __bfloat162float(h[j]));
  }
  ((uint2*)hi)[i] = *(uint2*)h;
  ((uint2*)lo)[i] = *(uint2*)l;
}

// Split V columns [2304, 2560) out of the fused QKV output into packed [M][256].
__global__ void split_v_strided(const float* __restrict__ qkv,
                                __nv_bfloat16* __restrict__ hi,
                                __nv_bfloat16* __restrict__ lo, int n4) {
  int i = blockIdx.x * blockDim.x + threadIdx.x;
  if (i >= n4) return;                   // n4 = M*64 (64 float4s per row)
  int row = i >> 6, c4 = i & 63;
  float4 v = *(const float4*)(qkv + (size_t)row * NCAT + (HID_C + KV_C * D_C) + c4 * 4);
  __nv_bfloat16 h[4], l[4];
  float f[4] = {v.x, v.y, v.z, v.w};
#pragma unroll
  for (int j = 0; j < 4; ++j) {
    h[j] = __float2bfloat16(f[j]);
    l[j] = __float2bfloat16(f[j] - __bfloat162float(h[j]));
  }
  ((uint2*)hi)[i] = *(uint2*)h;
  ((uint2*)lo)[i] = *(uint2*)l;
}

// ---------------------------------------------------------------------------
// bf16x3 split-precision NT GEMM (tensor cores) — proven in R2/R4/R7
// ---------------------------------------------------------------------------
constexpr int LDAB = 40;
constexpr int GTILE = 128 * LDAB;
constexpr int GTILE_B = GTILE * 2;
constexpr int GEMM_SMEM = 8 * GTILE_B;

template <bool HAS_BIAS>
__global__ void __launch_bounds__(256, 1)
gemm_bf16x3(const __nv_bfloat16* __restrict__ Ah, const __nv_bfloat16* __restrict__ Al,
            const __nv_bfloat16* __restrict__ Bh, const __nv_bfloat16* __restrict__ Bl,
            const float* __restrict__ bias, float* __restrict__ C,
            int M, int N, int K) {
  extern __shared__ __nv_bfloat16 smb[];
  __nv_bfloat16* sAh = smb;
  __nv_bfloat16* sAl = smb + 2 * GTILE;
  __nv_bfloat16* sBh = smb + 4 * GTILE;
  __nv_bfloat16* sBl = smb + 6 * GTILE;

  const int tid = threadIdx.x;
  const int lane = tid & 31, wid = tid >> 5;
  const int wm = wid & 1, wn = wid >> 1;
  const int m0 = blockIdx.y * 128, n0 = blockIdx.x * 128;

  const int lrow = tid >> 2;
  const int lcol = (tid & 3) * 8;
  const size_t aoff = (size_t)(m0 + lrow) * K + lcol;
  const size_t boff = (size_t)(n0 + lrow) * K + lcol;
  const uint32_t sdst = (uint32_t)((lrow * LDAB + lcol) * 2);
  const uint32_t sAh0 = smem_u32(sAh) + sdst;
  const uint32_t sAl0 = smem_u32(sAl) + sdst;
  const uint32_t sBh0 = smem_u32(sBh) + sdst;
  const uint32_t sBl0 = smem_u32(sBl) + sdst;
  constexpr uint32_t RSTEP = 64 * LDAB * 2;

  const int KT = K / 32;

  auto load_tile = [&](int kt, int buf) {
    const size_t g = (size_t)kt * 32;
    const uint32_t so = (uint32_t)buf * GTILE_B;
    const size_t a2 = aoff + g, b2 = boff + g;
    cp_async16(sAh0 + so,         Ah + a2);
    cp_async16(sAh0 + so + RSTEP, Ah + a2 + (size_t)64 * K);
    cp_async16(sAl0 + so,         Al + a2);
    cp_async16(sAl0 + so + RSTEP, Al + a2 + (size_t)64 * K);
    cp_async16(sBh0 + so,         Bh + b2);
    cp_async16(sBh0 + so + RSTEP, Bh + b2 + (size_t)64 * K);
    cp_async16(sBl0 + so,         Bl + b2);
    cp_async16(sBl0 + so + RSTEP, Bl + b2 + (size_t)64 * K);
  };

  load_tile(0, 0);
  cp_commit();

  float acc[4][4][4];
#pragma unroll
  for (int i = 0; i < 4; ++i)
#pragma unroll
    for (int j = 0; j < 4; ++j)
#pragma unroll
      for (int r = 0; r < 4; ++r) acc[i][j][r] = 0.f;

  const int arow = wm * 64 + (lane & 15);
  const int acolx = ((lane >> 4) << 3);
  const int brow = wn * 32 + ((lane >> 4) << 3) + (lane & 7);
  const int bcolx = (((lane >> 3) & 1) << 3);
  const uint32_t sAhB = smem_u32(sAh), sAlB = smem_u32(sAl);
  const uint32_t sBhB = smem_u32(sBh), sBlB = smem_u32(sBl);

  for (int kt = 0; kt < KT; ++kt) {
    const int buf = kt & 1;
    if (kt + 1 < KT) {
      load_tile(kt + 1, buf ^ 1);
      cp_commit();
      cp_wait1();
    } else {
      cp_wait0();
    }
    __syncthreads();

    const uint32_t so = (uint32_t)buf * GTILE_B;
#pragma unroll
    for (int k2 = 0; k2 < 2; ++k2) {
      uint32_t afh[4][4], afl[4][4], bfh[4][2], bfl[4][2];
      const uint32_t acol = k2 * 16 + acolx;
      const uint32_t bcol = k2 * 16 + bcolx;
#pragma unroll
      for (int mt = 0; mt < 4; ++mt) {
        const uint32_t ao = so + (uint32_t)(((arow + mt * 16) * LDAB + acol) * 2);
        ldmx4(afh[mt], sAhB + ao);
        ldmx4(afl[mt], sAlB + ao);
      }
#pragma unroll
      for (int nt2 = 0; nt2 < 2; ++nt2) {
        uint32_t t[4];
        const uint32_t bo = so + (uint32_t)(((brow + nt2 * 16) * LDAB + bcol) * 2);
        ldmx4(t, sBhB + bo);
        bfh[nt2 * 2][0] = t[0]; bfh[nt2 * 2][1] = t[1];
        bfh[nt2 * 2 + 1][0] = t[2]; bfh[nt2 * 2 + 1][1] = t[3];
        ldmx4(t, sBlB + bo);
        bfl[nt2 * 2][0] = t[0]; bfl[nt2 * 2][1] = t[1];
        bfl[nt2 * 2 + 1][0] = t[2]; bfl[nt2 * 2 + 1][1] = t[3];
      }
#pragma unroll
      for (int mt = 0; mt < 4; ++mt)
#pragma unroll
        for (int nt = 0; nt < 4; ++nt) {
          mma_bf16(acc[mt][nt], afh[mt], bfh[nt][0], bfh[nt][1]);
          mma_bf16(acc[mt][nt], afh[mt], bfl[nt][0], bfl[nt][1]);
          mma_bf16(acc[mt][nt], afl[mt], bfh[nt][0], bfh[nt][1]);
        }
    }
    __syncthreads();
  }

  float2 bv[4];
#pragma unroll
  for (int nt = 0; nt < 4; ++nt) {
    const int col = n0 + wn * 32 + nt * 8 + (lane & 3) * 2;
    if (HAS_BIAS) { bv[nt].x = bias[col]; bv[nt].y = bias[col + 1]; }
    else          { bv[nt].x = 0.f;       bv[nt].y = 0.f; }
  }
#pragma unroll
  for (int mt = 0; mt < 4; ++mt) {
    const int r0 = m0 + wm * 64 + mt * 16 + (lane >> 2);
#pragma unroll
    for (int nt = 0; nt < 4; ++nt) {
      const int col = n0 + wn * 32 + nt * 8 + (lane & 3) * 2;
      float2 v0 = make_float2(acc[mt][nt][0] + bv[nt].x, acc[mt][nt][1] + bv[nt].y);
      float2 v1 = make_float2(acc[mt][nt][2] + bv[nt].x, acc[mt][nt][3] + bv[nt].y);
      *(float2*)(C + (size_t)r0 * N + col) = v0;
      *(float2*)(C + (size_t)(r0 + 8) * N + col) = v1;
    }
  }
}

// ---------------------------------------------------------------------------
// RoPE + bf16 hi/lo split (fused). Reads q,k from the fused QKV buffer.
// ---------------------------------------------------------------------------
__global__ void rope_split(const float* __restrict__ qkv,
                           const float* __restrict__ cs, const float* __restrict__ sn,
                           __nv_bfloat16* __restrict__ qh, __nv_bfloat16* __restrict__ ql,
                           __nv_bfloat16* __restrict__ kh, __nv_bfloat16* __restrict__ kl,
                           int Lr, int Mr) {
  const int per = (H_C + KV_C) * 64;
  int t = blockIdx.x * blockDim.x + threadIdx.x;
  if (t >= Mr * per) return;
  int row = t / per;
  int rem = t - row * per;
  int hd = rem >> 6;
  int d = rem & 63;
  int l = row % Lr;
  float c = cs[l * 128 + d];
  float s = sn[l * 128 + d];
  const float* p;
  __nv_bfloat16 *oh, *ol;
  if (hd < H_C) {
    p  = qkv + (size_t)row * NCAT + hd * D_C;
    size_t ob = (size_t)row * HID_C + hd * D_C;
    oh = qh + ob; ol = ql + ob;
  } else {
    p  = qkv + (size_t)row * NCAT + HID_C + (hd - H_C) * D_C;
    size_t ob = (size_t)row * (KV_C * D_C) + (hd - H_C) * D_C;
    oh = kh + ob; ol = kl + ob;
  }
  float x1 = p[d], x2 = p[d + 64];
  float y1 = x1 * c - x2 * s;
  float y2 = x2 * c + x1 * s;
  __nv_bfloat16 h1 = __float2bfloat16(y1);
  __nv_bfloat16 h2 = __float2bfloat16(y2);
  oh[d]      = h1;  ol[d]      = __float2bfloat16(y1 - __bfloat162float(h1));
  oh[d + 64] = h2;  ol[d + 64] = __float2bfloat16(y2 - __bfloat162float(h2));
}

// ---------------------------------------------------------------------------
// Flash attention, bf16x3 MMA, 64x64 tiles, 8 warps (4m x 2n), causal, GQA.
// DOUBLE-BUFFERED K/V stages: next tile's loads overlap this tile's compute.
// ---------------------------------------------------------------------------
constexpr int LDK = 136;
constexpr int LDP = 72;
constexpr int ROWS_T = 64 * LDK;                 // one 64x128(+pad) tile, bf16 elems
constexpr int QH_OFF = 0;
constexpr int QL_OFF = ROWS_T;
constexpr int STG0   = 2 * ROWS_T;               // stage 0 base
constexpr int STG_SZ = 4 * ROWS_T;               // KH,KL,VH,VL
constexpr int KH_O = 0, KL_O = ROWS_T, VH_O = 2 * ROWS_T, VL_O = 3 * ROWS_T;
constexpr int PH_OFF = STG0 + 2 * STG_SZ;
constexpr int PL_OFF = PH_OFF + 64 * LDP;
constexpr int RED_OFF = PL_OFF + 64 * LDP;       // bf16-elem offset of stats
constexpr int FLASH3_SMEM = RED_OFF * 2 + 2 * 128 * 4;   // 193536 bytes

__global__ void __launch_bounds__(256, 1)
flash_mma(const __nv_bfloat16* __restrict__ Qh, const __nv_bfloat16* __restrict__ Ql,
          const __nv_bfloat16* __restrict__ Kh, const __nv_bfloat16* __restrict__ Kl,
          const __nv_bfloat16* __restrict__ Vh, const __nv_bfloat16* __restrict__ Vl,
          __nv_bfloat16* __restrict__ Oh, __nv_bfloat16* __restrict__ Ol, int Lr) {
  extern __shared__ __nv_bfloat16 sb[];
  const uint32_t sbase = smem_u32(sb);
  float* redm = (float*)(sb + RED_OFF);
  float* reds = redm + 128;

  const int qt = blockIdx.x, h = blockIdx.y, b = blockIdx.z;
  const int kvh = h >> 3;
  const int q0 = qt * 64;
  const int tid = threadIdx.x, lane = tid & 31, w = tid >> 5;
  const int wm = w & 3, wn = w >> 2;

  const int lr = tid & 63, lcg = tid >> 6;
  const uint32_t sd = (uint32_t)((lr * LDK + lcg * 32) * 2);

  // ---- Q tile (own group, loaded once) ----
  {
    const size_t grow = (size_t)(b * Lr + q0 + lr) * HID_C + h * D_C + lcg * 32;
#pragma unroll
    for (int i = 0; i < 4; ++i) {
      cp_async16(sbase + QH_OFF * 2 + sd + i * 16, Qh + grow + i * 8);
      cp_async16(sbase + QL_OFF * 2 + sd + i * 16, Ql + grow + i * 8);
    }
    cp_commit();
  }

  // stage loader: K+V hi/lo for tile kt into stage s (one commit group)
  auto load_stage = [&](int kt, int s) {
    const size_t gr = (size_t)(b * Lr + kt * 64 + lr) * (KV_C * D_C) + kvh * D_C + lcg * 32;
    const uint32_t sg = sbase + (uint32_t)(STG0 + s * STG_SZ) * 2 + sd;
#pragma unroll
    for (int i = 0; i < 4; ++i) {
      cp_async16(sg + KH_O * 2 + i * 16, Kh + gr + i * 8);
      cp_async16(sg + KL_O * 2 + i * 16, Kl + gr + i * 8);
      cp_async16(sg + VH_O * 2 + i * 16, Vh + gr + i * 8);
      cp_async16(sg + VL_O * 2 + i * 16, Vl + gr + i * 8);
    }
    cp_commit();
  };

  load_stage(0, 0);   // prologue stage

  const int rq = lane >> 2, tq = lane & 3;
  const int arow = wm * 16 + (lane & 15);
  const int kcol8 = (lane >> 4) << 3;
  const int brow = wn * 32 + kcol8 + (lane & 7);
  const int bcol8 = ((lane >> 3) & 1) << 3;
  const int vrow = lane & 15;
  const int row0 = wm * 16 + rq;

  float m0 = -1e30f, m1 = -1e30f, l0 = 0.f, l1 = 0.f;
  float oacc[8][4];
#pragma unroll
  for (int i = 0; i < 8; ++i)
#pragma unroll
    for (int j = 0; j < 4; ++j) oacc[i][j] = 0.f;

  const float scale = 0.08838834764831845f;

  for (int kt = 0; kt <= qt; ++kt) {
    const int buf = kt & 1;
    if (kt + 1 <= qt) {
      __syncthreads();                 // prior reads of buf^1 complete
      load_stage(kt + 1, buf ^ 1);     // prefetch next stage
      cp_wait1();                      // stage kt (and Q) ready
    } else {
      cp_wait0();
    }
    __syncthreads();

    const uint32_t KHB = sbase + (uint32_t)(STG0 + buf * STG_SZ + KH_O) * 2;
    const uint32_t KLB = sbase + (uint32_t)(STG0 + buf * STG_SZ + KL_O) * 2;
    const uint32_t VHB = sbase + (uint32_t)(STG0 + buf * STG_SZ + VH_O) * 2;
    const uint32_t VLB = sbase + (uint32_t)(STG0 + buf * STG_SZ + VL_O) * 2;

    // ---- S = Q K^T (3-term bf16x3) ----
    float sa[4][4];
#pragma unroll
    for (int i = 0; i < 4; ++i)
#pragma unroll
      for (int j = 0; j < 4; ++j) sa[i][j] = 0.f;

#pragma unroll
    for (int kst = 0; kst < 8; ++kst) {
      uint32_t ah4[4], al4[4];
      const uint32_t ao = (uint32_t)((arow * LDK + kst * 16 + kcol8) * 2);
      ldmx4(ah4, sbase + QH_OFF * 2 + ao);
      ldmx4(al4, sbase + QL_OFF * 2 + ao);
      uint32_t bh[4][2], bl[4][2];
#pragma unroll
      for (int nt2 = 0; nt2 < 2; ++nt2) {
        uint32_t t4[4];
        const uint32_t bo = (uint32_t)(((brow + nt2 * 16) * LDK + kst * 16 + bcol8) * 2);
        ldmx4(t4, KHB + bo);
        bh[nt2 * 2][0] = t4[0]; bh[nt2 * 2][1] = t4[1];
        bh[nt2 * 2 + 1][0] = t4[2]; bh[nt2 * 2 + 1][1] = t4[3];
        ldmx4(t4, KLB + bo);
        bl[nt2 * 2][0] = t4[0]; bl[nt2 * 2][1] = t4[1];
        bl[nt2 * 2 + 1][0] = t4[2]; bl[nt2 * 2 + 1][1] = t4[3];
      }
#pragma unroll
      for (int nf = 0; nf < 4; ++nf) {
        mma_bf16(sa[nf], ah4, bh[nf][0], bh[nf][1]);
        mma_bf16(sa[nf], ah4, bl[nf][0], bl[nf][1]);
        mma_bf16(sa[nf], al4, bh[nf][0], bh[nf][1]);
      }
    }

    // ---- scale + causal mask + partial row max ----
    const bool diag = (kt == qt);
    float tmx0 = -1e30f, tmx1 = -1e30f;
#pragma unroll
    for (int nf = 0; nf < 4; ++nf) {
#pragma unroll
      for (int j = 0; j < 4; ++j) {
        float sv = sa[nf][j] * scale;
        if (diag) {
          const int col = wn * 32 + nf * 8 + 2 * tq + (j & 1);
          const int rowl = row0 + ((j >= 2) ? 8 : 0);
          if (col > rowl) sv = -1e30f;
        }
        sa[nf][j] = sv;
        if (j < 2) tmx0 = fmaxf(tmx0, sv); else tmx1 = fmaxf(tmx1, sv);
      }
    }
    tmx0 = fmaxf(tmx0, __shfl_xor_sync(0xffffffffu, tmx0, 1));
    tmx0 = fmaxf(tmx0, __shfl_xor_sync(0xffffffffu, tmx0, 2));
    tmx1 = fmaxf(tmx1, __shfl_xor_sync(0xffffffffu, tmx1, 1));
    tmx1 = fmaxf(tmx1, __shfl_xor_sync(0xffffffffu, tmx1, 2));
    if (tq == 0) {
      redm[wn * 64 + row0] = tmx0;
      redm[wn * 64 + row0 + 8] = tmx1;
    }
    __syncthreads();   // barrier A

    const float fm0 = fmaxf(redm[row0], redm[64 + row0]);
    const float fm1 = fmaxf(redm[row0 + 8], redm[64 + row0 + 8]);
    const float mn0 = fmaxf(m0, fm0), mn1 = fmaxf(m1, fm1);
    const float al0 = __expf(m0 - mn0), al1 = __expf(m1 - mn1);
    m0 = mn0; m1 = mn1;

    float rs0 = 0.f, rs1 = 0.f;
#pragma unroll
    for (int nf = 0; nf < 4; ++nf) {
      float p0 = __expf(sa[nf][0] - mn0);
      float p1 = __expf(sa[nf][1] - mn0);
      float p2 = __expf(sa[nf][2] - mn1);
      float p3 = __expf(sa[nf][3] - mn1);
      rs0 += p0 + p1; rs1 += p2 + p3;
      sa[nf][0] = p0; sa[nf][1] = p1; sa[nf][2] = p2; sa[nf][3] = p3;
    }
    rs0 += __shfl_xor_sync(0xffffffffu, rs0, 1);
    rs0 += __shfl_xor_sync(0xffffffffu, rs0, 2);
    rs1 += __shfl_xor_sync(0xffffffffu, rs1, 1);
    rs1 += __shfl_xor_sync(0xffffffffu, rs1, 2);
    if (tq == 0) {
      reds[wn * 64 + row0] = rs0;
      reds[wn * 64 + row0 + 8] = rs1;
    }

#pragma unroll
    for (int nf = 0; nf < 8; ++nf) {
      oacc[nf][0] *= al0; oacc[nf][1] *= al0;
      oacc[nf][2] *= al1; oacc[nf][3] *= al1;
    }

    // ---- write P (bf16 hi/lo) ----
#pragma unroll
    for (int nf = 0; nf < 4; ++nf) {
      const int pcol = wn * 32 + nf * 8 + 2 * tq;
      __nv_bfloat16 h0 = __float2bfloat16(sa[nf][0]);
      __nv_bfloat16 h1 = __float2bfloat16(sa[nf][1]);
      __nv_bfloat16 h2 = __float2bfloat16(sa[nf][2]);
      __nv_bfloat16 h3 = __float2bfloat16(sa[nf][3]);
      __nv_bfloat162 ph01; ph01.x = h0; ph01.y = h1;
      __nv_bfloat162 ph23; ph23.x = h2; ph23.y = h3;
      __nv_bfloat162 pl01, pl23;
      pl01.x = __float2bfloat16(sa[nf][0] - __bfloat162float(h0));
      pl01.y = __float2bfloat16(sa[nf][1] - __bfloat162float(h1));
      pl23.x = __float2bfloat16(sa[nf][2] - __bfloat162float(h2));
      pl23.y = __float2bfloat16(sa[nf][3] - __bfloat162float(h3));
      *(__nv_bfloat162*)(sb + PH_OFF + row0 * LDP + pcol) = ph01;
      *(__nv_bfloat162*)(sb + PH_OFF + (row0 + 8) * LDP + pcol) = ph23;
      *(__nv_bfloat162*)(sb + PL_OFF + row0 * LDP + pcol) = pl01;
      *(__nv_bfloat162*)(sb + PL_OFF + (row0 + 8) * LDP + pcol) = pl23;
    }
    __syncthreads();   // barrier B (P + sums visible; V already resident)

    l0 = l0 * al0 + (reds[row0] + reds[64 + row0]);
    l1 = l1 * al1 + (reds[row0 + 8] + reds[64 + row0 + 8]);

    // ---- O += P V (V fragments via ldmatrix.trans) ----
#pragma unroll
    for (int k0i = 0; k0i < 64; k0i += 16) {
      uint32_t pah[4], pal[4];
      const uint32_t po = (uint32_t)((arow * LDP + k0i + kcol8) * 2);
      ldmx4(pah, sbase + PH_OFF * 2 + po);
      ldmx4(pal, sbase + PL_OFF * 2 + po);
#pragma unroll
      for (int df = 0; df < 4; ++df) {
        uint32_t th[4], tl[4];
        const uint32_t bo = (uint32_t)(((k0i + vrow) * LDK + wn * 64 + df * 16 + kcol8) * 2);
        ldmx4t(th, VHB + bo);
        ldmx4t(tl, VLB + bo);
        mma_bf16(oacc[df * 2],     pah, th[0], th[1]);
        mma_bf16(oacc[df * 2],     pah, tl[0], tl[1]);
        mma_bf16(oacc[df * 2],     pal, th[0], th[1]);
        mma_bf16(oacc[df * 2 + 1], pah, th[2], th[3]);
        mma_bf16(oacc[df * 2 + 1], pah, tl[2], tl[3]);
        mma_bf16(oacc[df * 2 + 1], pal, th[2], th[3]);
      }
    }
  }

  // ---- normalize + write bf16 hi/lo output ----
  const float inv0 = 1.f / l0, inv1 = 1.f / l1;
  const size_t gr0 = (size_t)(b * Lr + q0 + row0) * HID_C;
  const size_t gr1 = gr0 + (size_t)8 * HID_C;
#pragma unroll
  for (int nf = 0; nf < 8; ++nf) {
    const int col = h * D_C + wn * 64 + nf * 8 + 2 * tq;
    float o0 = oacc[nf][0] * inv0, o1 = oacc[nf][1] * inv0;
    float o2 = oacc[nf][2] * inv1, o3 = oacc[nf][3] * inv1;
    __nv_bfloat162 h01, h23, l01, l23;
    h01.x = __float2bfloat16(o0); h01.y = __float2bfloat16(o1);
    h23.x = __float2bfloat16(o2); h23.y = __float2bfloat16(o3);
    l01.x = __float2bfloat16(o0 - __bfloat162float(h01.x));
    l01.y = __float2bfloat16(o1 - __bfloat162float(h01.y));
    l23.x = __float2bfloat16(o2 - __bfloat162float(h23.x));
    l23.y = __float2bfloat16(o3 - __bfloat162float(h23.y));
    *(__nv_bfloat162*)(Oh + gr0 + col) = h01;
    *(__nv_bfloat162*)(Oh + gr1 + col) = h23;
    *(__nv_bfloat162*)(Ol + gr0 + col) = l01;
    *(__nv_bfloat162*)(Ol + gr1 + col) = l23;
  }
}

// ---------------------------------------------------------------------------
// kernel_launch: x, cos, sin, wq, bq, wk, bk, wv, bv, wo
// ---------------------------------------------------------------------------
extern "C" void kernel_launch(void* const* d_in, const int* in_sizes, int n_in,
                              void* d_out, int out_size) {
  const float* x  = (const float*)d_in[0];
  const float* cs = (const float*)d_in[1];
  const float* sn = (const float*)d_in[2];
  const float* wq = (const float*)d_in[3];
  const float* bq = (const float*)d_in[4];
  const float* wk = (const float*)d_in[5];
  const float* bk = (const float*)d_in[6];
  const float* wv = (const float*)d_in[7];
  const float* bv = (const float*)d_in[8];
  const float* wo = (const float*)d_in[9];
  float* out = (float*)d_out;

  const int Lr = in_sizes[1] / 128;
  const int Mr = in_sizes[0] / HID_C;
  const int NKV = KV_C * D_C;

  void *qkvp, *bcp;
  void *xh, *xl, *wch, *wcl, *woh, *wol, *ah, *al;
  void *qhp, *qlp, *khp, *klp, *vhp, *vlp;
  cudaGetSymbolAddress(&qkvp, g_qkv);  cudaGetSymbolAddress(&bcp, g_bcat);
  cudaGetSymbolAddress(&xh, g_xh);     cudaGetSymbolAddress(&xl, g_xl);
  cudaGetSymbolAddress(&wch, g_wcath); cudaGetSymbolAddress(&wcl, g_wcatl);
  cudaGetSymbolAddress(&woh, g_woh);   cudaGetSymbolAddress(&wol, g_wol);
  cudaGetSymbolAddress(&ah, g_ah);     cudaGetSymbolAddress(&al, g_al);
  cudaGetSymbolAddress(&qhp, g_qh);    cudaGetSymbolAddress(&qlp, g_ql);
  cudaGetSymbolAddress(&khp, g_kh);    cudaGetSymbolAddress(&klp, g_kl);
  cudaGetSymbolAddress(&vhp, g_vh);    cudaGetSymbolAddress(&vlp, g_vl);

  cudaFuncSetAttribute(gemm_bf16x3<true>,  cudaFuncAttributeMaxDynamicSharedMemorySize, GEMM_SMEM);
  cudaFuncSetAttribute(gemm_bf16x3<false>, cudaFuncAttributeMaxDynamicSharedMemorySize, GEMM_SMEM);
  cudaFuncSetAttribute(flash_mma,          cudaFuncAttributeMaxDynamicSharedMemorySize, FLASH3_SMEM);

  dim3 blk(256);

  auto split = [&](const float* src, void* hi, void* lo, int n) {
    int n4 = n / 4;
    split_kernel<<<(n4 + 255) / 256, blk>>>(src, (__nv_bfloat16*)hi, (__nv_bfloat16*)lo, n4);
  };

  __nv_bfloat16* wcath = (__nv_bfloat16*)wch;
  __nv_bfloat16* wcatl = (__nv_bfloat16*)wcl;

  // launches 0-3: splits of x and QKV weights (into concat buffer)
  split(x,  xh, xl, Mr * HID_C);
  split(wq, wcath,                          wcatl,                          HID_C * HID_C);
  split(wk, wcath + (size_t)HID_C * HID_C,  wcatl + (size_t)HID_C * HID_C,  NKV * HID_C);
  split(wv, wcath + (size_t)(HID_C + NKV) * HID_C,
            wcatl + (size_t)(HID_C + NKV) * HID_C, NKV * HID_C);
  // launch 4: bias concat
  bias_concat<<<(NCAT + 255) / 256, blk>>>(bq, bk, bv, (float*)bcp);

  // launch 5: fused QKV projection (N=2560) — profiled by ncu -s 5
  dim3 gqkv(NCAT / 128, Mr / 128);
  gemm_bf16x3<true><<<gqkv, blk, GEMM_SMEM>>>(
      (const __nv_bfloat16*)xh, (const __nv_bfloat16*)xl,
      wcath, wcatl, (const float*)bcp, (float*)qkvp, Mr, NCAT, HID_C);

  // split wo
  split(wo, woh, wol, HID_C * HID_C);

  // RoPE + split q,k from fused buffer; split v from fused buffer
  const int rt = Mr * (H_C + KV_C) * 64;
  rope_split<<<(rt + 255) / 256, blk>>>((const float*)qkvp, cs, sn,
                                        (__nv_bfloat16*)qhp, (__nv_bfloat16*)qlp,
                                        (__nv_bfloat16*)khp, (__nv_bfloat16*)klp, Lr, Mr);
  {
    int n4 = Mr * 64;
    split_v_strided<<<(n4 + 255) / 256, blk>>>((const float*)qkvp,
                                               (__nv_bfloat16*)vhp, (__nv_bfloat16*)vlp, n4);
  }

  // Flash attention (double-buffered K/V stages)
  dim3 gf(Lr / 64, H_C, Mr / Lr);
  flash_mma<<<gf, blk, FLASH3_SMEM>>>(
      (const __nv_bfloat16*)qhp, (const __nv_bfloat16*)qlp,
      (const __nv_bfloat16*)khp, (const __nv_bfloat16*)klp,
      (const __nv_bfloat16*)vhp, (const __nv_bfloat16*)vlp,
      (__nv_bfloat16*)ah, (__nv_bfloat16*)al, Lr);

  // Output projection
  dim3 go(HID_C / 128, Mr / 128);
  gemm_bf16x3<false><<<go, blk, GEMM_SMEM>>>(
      (const __nv_bfloat16*)ah, (const __nv_bfloat16*)al,
      (const __nv_bfloat16*)woh, (const __nv_bfloat16*)wol,
      nullptr, out, Mr, HID_C, HID_C);
}

// round 9
// speedup vs baseline: 1.0579x; 1.0579x over previous
#include <cuda_runtime.h>
#include <cuda_bf16.h>
#include <cstdint>

// ---------------------------------------------------------------------------
// Problem constants
// ---------------------------------------------------------------------------
constexpr int HID_C = 2048;
constexpr int H_C   = 16;
constexpr int KV_C  = 2;
constexpr int D_C   = 128;
constexpr int MAXM  = 4096;
constexpr int NCAT  = HID_C + 2 * KV_C * D_C;   // 2560 fused QKV output cols

// ---------------------------------------------------------------------------
// Scratch (static __device__; no allocation anywhere)
// ---------------------------------------------------------------------------
__device__ float g_qkv[MAXM * NCAT];             // fused QKV projection output
__device__ float g_bcat[NCAT];                   // concat bias

__device__ __nv_bfloat16 g_xh[MAXM * HID_C],  g_xl[MAXM * HID_C];
__device__ __nv_bfloat16 g_wcath[NCAT * HID_C], g_wcatl[NCAT * HID_C];
__device__ __nv_bfloat16 g_woh[HID_C * HID_C], g_wol[HID_C * HID_C];
__device__ __nv_bfloat16 g_ah[MAXM * HID_C],  g_al[MAXM * HID_C];

__device__ __nv_bfloat16 g_qh[MAXM * HID_C],       g_ql[MAXM * HID_C];
__device__ __nv_bfloat16 g_kh[MAXM * KV_C * D_C],  g_kl[MAXM * KV_C * D_C];
__device__ __nv_bfloat16 g_vh[MAXM * KV_C * D_C],  g_vl[MAXM * KV_C * D_C];

// ---------------------------------------------------------------------------
// Helpers
// ---------------------------------------------------------------------------
__device__ __forceinline__ uint32_t smem_u32(const void* p) {
  return (uint32_t)__cvta_generic_to_shared(p);
}
__device__ __forceinline__ void cp_async16(uint32_t dst, const void* src) {
  asm volatile("cp.async.cg.shared.global [%0], [%1], 16;" :: "r"(dst), "l"(src));
}
__device__ __forceinline__ void cp_commit() { asm volatile("cp.async.commit_group;"); }
__device__ __forceinline__ void cp_wait1()  { asm volatile("cp.async.wait_group 1;"); }
__device__ __forceinline__ void cp_wait0()  { asm volatile("cp.async.wait_group 0;"); }

__device__ __forceinline__ void ldmx4(uint32_t (&r)[4], uint32_t addr) {
  asm volatile("ldmatrix.sync.aligned.m8n8.x4.shared.b16 {%0,%1,%2,%3}, [%4];"
               : "=r"(r[0]), "=r"(r[1]), "=r"(r[2]), "=r"(r[3]) : "r"(addr));
}
__device__ __forceinline__ void ldmx4t(uint32_t (&r)[4], uint32_t addr) {
  asm volatile("ldmatrix.sync.aligned.m8n8.x4.trans.shared.b16 {%0,%1,%2,%3}, [%4];"
               : "=r"(r[0]), "=r"(r[1]), "=r"(r[2]), "=r"(r[3]) : "r"(addr));
}
__device__ __forceinline__ void mma_bf16(float (&d)[4], const uint32_t (&a)[4],
                                         const uint32_t b0, const uint32_t b1) {
  asm volatile(
      "mma.sync.aligned.m16n8k16.row.col.f32.bf16.bf16.f32 "
      "{%0,%1,%2,%3}, {%4,%5,%6,%7}, {%8,%9}, {%0,%1,%2,%3};"
      : "+f"(d[0]), "+f"(d[1]), "+f"(d[2]), "+f"(d[3])
      : "r"(a[0]), "r"(a[1]), "r"(a[2]), "r"(a[3]), "r"(b0), "r"(b1));
}

// ---------------------------------------------------------------------------
// Small kernels: bias concat, fp32 -> bf16 hi/lo split (plain + strided)
// ---------------------------------------------------------------------------
__global__ void bias_concat(const float* __restrict__ bq, const float* __restrict__ bk,
                            const float* __restrict__ bv, float* __restrict__ bc) {
  int i = blockIdx.x * blockDim.x + threadIdx.x;
  if (i >= NCAT) return;
  float v;
  if (i < HID_C) v = bq[i];
  else if (i < HID_C + KV_C * D_C) v = bk[i - HID_C];
  else v = bv[i - HID_C - KV_C * D_C];
  bc[i] = v;
}

__global__ void split_kernel(const float* __restrict__ s, __nv_bfloat16* __restrict__ hi,
                             __nv_bfloat16* __restrict__ lo, int n4) {
  int i = blockIdx.x * blockDim.x + threadIdx.x;
  if (i >= n4) return;
  float4 v = ((const float4*)s)[i];
  __nv_bfloat16 h[4], l[4];
  float f[4] = {v.x, v.y, v.z, v.w};
#pragma unroll
  for (int j = 0; j < 4; ++j) {
    h[j] = __float2bfloat16(f[j]);
    l[j] = __float2bfloat16(f[j] - __bfloat162float(h[j]));
  }
  ((uint2*)hi)[i] = *(uint2*)h;
  ((uint2*)lo)[i] = *(uint2*)l;
}

// Split V columns [2304, 2560) out of the fused QKV output into packed [M][256].
__global__ void split_v_strided(const float* __restrict__ qkv,
                                __nv_bfloat16* __restrict__ hi,
                                __nv_bfloat16* __restrict__ lo, int n4) {
  int i = blockIdx.x * blockDim.x + threadIdx.x;
  if (i >= n4) return;                   // n4 = M*64 (64 float4s per row)
  int row = i >> 6, c4 = i & 63;
  float4 v = *(const float4*)(qkv + (size_t)row * NCAT + (HID_C + KV_C * D_C) + c4 * 4);
  __nv_bfloat16 h[4], l[4];
  float f[4] = {v.x, v.y, v.z, v.w};
#pragma unroll
  for (int j = 0; j < 4; ++j) {
    h[j] = __float2bfloat16(f[j]);
    l[j] = __float2bfloat16(f[j] - __bfloat162float(h[j]));
  }
  ((uint2*)hi)[i] = *(uint2*)h;
  ((uint2*)lo)[i] = *(uint2*)l;
}

// ---------------------------------------------------------------------------
// bf16x3 split-precision NT GEMM (tensor cores).
// R9 change: __launch_bounds__(256, 2) -> 2 CTAs/SM (regs capped at 128).
// Barrier/cp_wait bubbles of one CTA are filled by the co-resident CTA.
// ---------------------------------------------------------------------------
constexpr int LDAB = 40;
constexpr int GTILE = 128 * LDAB;
constexpr int GTILE_B = GTILE * 2;
constexpr int GEMM_SMEM = 8 * GTILE_B;           // 81920 B -> 2 CTAs fit in 228KB

template <bool HAS_BIAS>
__global__ void __launch_bounds__(256, 2)
gemm_bf16x3(const __nv_bfloat16* __restrict__ Ah, const __nv_bfloat16* __restrict__ Al,
            const __nv_bfloat16* __restrict__ Bh, const __nv_bfloat16* __restrict__ Bl,
            const float* __restrict__ bias, float* __restrict__ C,
            int M, int N, int K) {
  extern __shared__ __nv_bfloat16 smb[];
  __nv_bfloat16* sAh = smb;
  __nv_bfloat16* sAl = smb + 2 * GTILE;
  __nv_bfloat16* sBh = smb + 4 * GTILE;
  __nv_bfloat16* sBl = smb + 6 * GTILE;

  const int tid = threadIdx.x;
  const int lane = tid & 31, wid = tid >> 5;
  const int wm = wid & 1, wn = wid >> 1;
  const int m0 = blockIdx.y * 128, n0 = blockIdx.x * 128;

  const int lrow = tid >> 2;
  const int lcol = (tid & 3) * 8;
  const size_t aoff = (size_t)(m0 + lrow) * K + lcol;
  const size_t boff = (size_t)(n0 + lrow) * K + lcol;
  const uint32_t sdst = (uint32_t)((lrow * LDAB + lcol) * 2);
  const uint32_t sAh0 = smem_u32(sAh) + sdst;
  const uint32_t sAl0 = smem_u32(sAl) + sdst;
  const uint32_t sBh0 = smem_u32(sBh) + sdst;
  const uint32_t sBl0 = smem_u32(sBl) + sdst;
  constexpr uint32_t RSTEP = 64 * LDAB * 2;

  const int KT = K / 32;

  auto load_tile = [&](int kt, int buf) {
    const size_t g = (size_t)kt * 32;
    const uint32_t so = (uint32_t)buf * GTILE_B;
    const size_t a2 = aoff + g, b2 = boff + g;
    cp_async16(sAh0 + so,         Ah + a2);
    cp_async16(sAh0 + so + RSTEP, Ah + a2 + (size_t)64 * K);
    cp_async16(sAl0 + so,         Al + a2);
    cp_async16(sAl0 + so + RSTEP, Al + a2 + (size_t)64 * K);
    cp_async16(sBh0 + so,         Bh + b2);
    cp_async16(sBh0 + so + RSTEP, Bh + b2 + (size_t)64 * K);
    cp_async16(sBl0 + so,         Bl + b2);
    cp_async16(sBl0 + so + RSTEP, Bl + b2 + (size_t)64 * K);
  };

  load_tile(0, 0);
  cp_commit();

  float acc[4][4][4];
#pragma unroll
  for (int i = 0; i < 4; ++i)
#pragma unroll
    for (int j = 0; j < 4; ++j)
#pragma unroll
      for (int r = 0; r < 4; ++r) acc[i][j][r] = 0.f;

  const int arow = wm * 64 + (lane & 15);
  const int acolx = ((lane >> 4) << 3);
  const int brow = wn * 32 + ((lane >> 4) << 3) + (lane & 7);
  const int bcolx = (((lane >> 3) & 1) << 3);
  const uint32_t sAhB = smem_u32(sAh), sAlB = smem_u32(sAl);
  const uint32_t sBhB = smem_u32(sBh), sBlB = smem_u32(sBl);

  for (int kt = 0; kt < KT; ++kt) {
    const int buf = kt & 1;
    if (kt + 1 < KT) {
      load_tile(kt + 1, buf ^ 1);
      cp_commit();
      cp_wait1();
    } else {
      cp_wait0();
    }
    __syncthreads();

    const uint32_t so = (uint32_t)buf * GTILE_B;
#pragma unroll
    for (int k2 = 0; k2 < 2; ++k2) {
      uint32_t afh[4][4], afl[4][4], bfh[4][2], bfl[4][2];
      const uint32_t acol = k2 * 16 + acolx;
      const uint32_t bcol = k2 * 16 + bcolx;
#pragma unroll
      for (int mt = 0; mt < 4; ++mt) {
        const uint32_t ao = so + (uint32_t)(((arow + mt * 16) * LDAB + acol) * 2);
        ldmx4(afh[mt], sAhB + ao);
        ldmx4(afl[mt], sAlB + ao);
      }
#pragma unroll
      for (int nt2 = 0; nt2 < 2; ++nt2) {
        uint32_t t[4];
        const uint32_t bo = so + (uint32_t)(((brow + nt2 * 16) * LDAB + bcol) * 2);
        ldmx4(t, sBhB + bo);
        bfh[nt2 * 2][0] = t[0]; bfh[nt2 * 2][1] = t[1];
        bfh[nt2 * 2 + 1][0] = t[2]; bfh[nt2 * 2 + 1][1] = t[3];
        ldmx4(t, sBlB + bo);
        bfl[nt2 * 2][0] = t[0]; bfl[nt2 * 2][1] = t[1];
        bfl[nt2 * 2 + 1][0] = t[2]; bfl[nt2 * 2 + 1][1] = t[3];
      }
#pragma unroll
      for (int mt = 0; mt < 4; ++mt)
#pragma unroll
        for (int nt = 0; nt < 4; ++nt) {
          mma_bf16(acc[mt][nt], afh[mt], bfh[nt][0], bfh[nt][1]);
          mma_bf16(acc[mt][nt], afh[mt], bfl[nt][0], bfl[nt][1]);
          mma_bf16(acc[mt][nt], afl[mt], bfh[nt][0], bfh[nt][1]);
        }
    }
    __syncthreads();
  }

  float2 bv[4];
#pragma unroll
  for (int nt = 0; nt < 4; ++nt) {
    const int col = n0 + wn * 32 + nt * 8 + (lane & 3) * 2;
    if (HAS_BIAS) { bv[nt].x = bias[col]; bv[nt].y = bias[col + 1]; }
    else          { bv[nt].x = 0.f;       bv[nt].y = 0.f; }
  }
#pragma unroll
  for (int mt = 0; mt < 4; ++mt) {
    const int r0 = m0 + wm * 64 + mt * 16 + (lane >> 2);
#pragma unroll
    for (int nt = 0; nt < 4; ++nt) {
      const int col = n0 + wn * 32 + nt * 8 + (lane & 3) * 2;
      float2 v0 = make_float2(acc[mt][nt][0] + bv[nt].x, acc[mt][nt][1] + bv[nt].y);
      float2 v1 = make_float2(acc[mt][nt][2] + bv[nt].x, acc[mt][nt][3] + bv[nt].y);
      *(float2*)(C + (size_t)r0 * N + col) = v0;
      *(float2*)(C + (size_t)(r0 + 8) * N + col) = v1;
    }
  }
}

// ---------------------------------------------------------------------------
// RoPE + bf16 hi/lo split (fused). Reads q,k from the fused QKV buffer.
// ---------------------------------------------------------------------------
__global__ void rope_split(const float* __restrict__ qkv,
                           const float* __restrict__ cs, const float* __restrict__ sn,
                           __nv_bfloat16* __restrict__ qh, __nv_bfloat16* __restrict__ ql,
                           __nv_bfloat16* __restrict__ kh, __nv_bfloat16* __restrict__ kl,
                           int Lr, int Mr) {
  const int per = (H_C + KV_C) * 64;
  int t = blockIdx.x * blockDim.x + threadIdx.x;
  if (t >= Mr * per) return;
  int row = t / per;
  int rem = t - row * per;
  int hd = rem >> 6;
  int d = rem & 63;
  int l = row % Lr;
  float c = cs[l * 128 + d];
  float s = sn[l * 128 + d];
  const float* p;
  __nv_bfloat16 *oh, *ol;
  if (hd < H_C) {
    p  = qkv + (size_t)row * NCAT + hd * D_C;
    size_t ob = (size_t)row * HID_C + hd * D_C;
    oh = qh + ob; ol = ql + ob;
  } else {
    p  = qkv + (size_t)row * NCAT + HID_C + (hd - H_C) * D_C;
    size_t ob = (size_t)row * (KV_C * D_C) + (hd - H_C) * D_C;
    oh = kh + ob; ol = kl + ob;
  }
  float x1 = p[d], x2 = p[d + 64];
  float y1 = x1 * c - x2 * s;
  float y2 = x2 * c + x1 * s;
  __nv_bfloat16 h1 = __float2bfloat16(y1);
  __nv_bfloat16 h2 = __float2bfloat16(y2);
  oh[d]      = h1;  ol[d]      = __float2bfloat16(y1 - __bfloat162float(h1));
  oh[d + 64] = h2;  ol[d + 64] = __float2bfloat16(y2 - __bfloat162float(h2));
}

// ---------------------------------------------------------------------------
// Flash attention (R7 version — best known). bf16x3 MMA, 64x64 tiles,
// 8 warps (4m x 2n), causal, GQA. K and V in separate cp.async groups.
// ---------------------------------------------------------------------------
constexpr int LDK = 136;
constexpr int LDP = 72;
constexpr int SM_QH = 0;
constexpr int SM_QL = 1 * 64 * LDK;
constexpr int SM_KH = 2 * 64 * LDK;
constexpr int SM_KL = 3 * 64 * LDK;
constexpr int SM_VH = 4 * 64 * LDK;
constexpr int SM_VL = 5 * 64 * LDK;
constexpr int SM_PH = 6 * 64 * LDK;
constexpr int SM_PL = 6 * 64 * LDK + 64 * LDP;
constexpr int SM_RED = 6 * 64 * LDK + 2 * 64 * LDP;
constexpr int FLASH2_SMEM = SM_RED * 2 + 2 * 128 * 4;

__global__ void __launch_bounds__(256, 1)
flash_mma(const __nv_bfloat16* __restrict__ Qh, const __nv_bfloat16* __restrict__ Ql,
          const __nv_bfloat16* __restrict__ Kh, const __nv_bfloat16* __restrict__ Kl,
          const __nv_bfloat16* __restrict__ Vh, const __nv_bfloat16* __restrict__ Vl,
          __nv_bfloat16* __restrict__ Oh, __nv_bfloat16* __restrict__ Ol, int Lr) {
  extern __shared__ __nv_bfloat16 sb[];
  const uint32_t sbase = smem_u32(sb);
  float* redm = (float*)(sb + SM_RED);
  float* reds = redm + 128;

  const int qt = blockIdx.x, h = blockIdx.y, b = blockIdx.z;
  const int kvh = h >> 3;
  const int q0 = qt * 64;
  const int tid = threadIdx.x, lane = tid & 31, w = tid >> 5;
  const int wm = w & 3, wn = w >> 2;

  const int lr = tid & 63, lcg = tid >> 6;

  {
    const size_t grow = (size_t)(b * Lr + q0 + lr) * HID_C + h * D_C + lcg * 32;
    const uint32_t sd = (uint32_t)((lr * LDK + lcg * 32) * 2);
#pragma unroll
    for (int i = 0; i < 4; ++i) {
      cp_async16(sbase + SM_QH * 2 + sd + i * 16, Qh + grow + i * 8);
      cp_async16(sbase + SM_QL * 2 + sd + i * 16, Ql + grow + i * 8);
    }
    cp_commit();
  }

  const int rq = lane >> 2, tq = lane & 3;
  const int arow = wm * 16 + (lane & 15);
  const int kcol8 = (lane >> 4) << 3;
  const int brow = wn * 32 + kcol8 + (lane & 7);
  const int bcol8 = ((lane >> 3) & 1) << 3;
  const int vrow = lane & 15;
  const int row0 = wm * 16 + rq;

  float m0 = -1e30f, m1 = -1e30f, l0 = 0.f, l1 = 0.f;
  float oacc[8][4];
#pragma unroll
  for (int i = 0; i < 8; ++i)
#pragma unroll
    for (int j = 0; j < 4; ++j) oacc[i][j] = 0.f;

  const float scale = 0.08838834764831845f;

  for (int kt = 0; kt <= qt; ++kt) {
    const int k0 = kt * 64;
    __syncthreads();
    {
      const size_t gr = (size_t)(b * Lr + k0 + lr) * (KV_C * D_C) + kvh * D_C + lcg * 32;
      const uint32_t sd = (uint32_t)((lr * LDK + lcg * 32) * 2);
#pragma unroll
      for (int i = 0; i < 4; ++i) {
        cp_async16(sbase + SM_KH * 2 + sd + i * 16, Kh + gr + i * 8);
        cp_async16(sbase + SM_KL * 2 + sd + i * 16, Kl + gr + i * 8);
      }
      cp_commit();                       // K group
#pragma unroll
      for (int i = 0; i < 4; ++i) {
        cp_async16(sbase + SM_VH * 2 + sd + i * 16, Vh + gr + i * 8);
        cp_async16(sbase + SM_VL * 2 + sd + i * 16, Vl + gr + i * 8);
      }
      cp_commit();                       // V group
    }
    cp_wait1();                          // K (and Q) ready; V still in flight
    __syncthreads();

    float sa[4][4];
#pragma unroll
    for (int i = 0; i < 4; ++i)
#pragma unroll
      for (int j = 0; j < 4; ++j) sa[i][j] = 0.f;

#pragma unroll
    for (int kst = 0; kst < 8; ++kst) {
      uint32_t ah4[4], al4[4];
      const uint32_t ao = (uint32_t)((arow * LDK + kst * 16 + kcol8) * 2);
      ldmx4(ah4, sbase + SM_QH * 2 + ao);
      ldmx4(al4, sbase + SM_QL * 2 + ao);
      uint32_t bh[4][2], bl[4][2];
#pragma unroll
      for (int nt2 = 0; nt2 < 2; ++nt2) {
        uint32_t t4[4];
        const uint32_t bo = (uint32_t)(((brow + nt2 * 16) * LDK + kst * 16 + bcol8) * 2);
        ldmx4(t4, sbase + SM_KH * 2 + bo);
        bh[nt2 * 2][0] = t4[0]; bh[nt2 * 2][1] = t4[1];
        bh[nt2 * 2 + 1][0] = t4[2]; bh[nt2 * 2 + 1][1] = t4[3];
        ldmx4(t4, sbase + SM_KL * 2 + bo);
        bl[nt2 * 2][0] = t4[0]; bl[nt2 * 2][1] = t4[1];
        bl[nt2 * 2 + 1][0] = t4[2]; bl[nt2 * 2 + 1][1] = t4[3];
      }
#pragma unroll
      for (int nf = 0; nf < 4; ++nf) {
        mma_bf16(sa[nf], ah4, bh[nf][0], bh[nf][1]);
        mma_bf16(sa[nf], ah4, bl[nf][0], bl[nf][1]);
        mma_bf16(sa[nf], al4, bh[nf][0], bh[nf][1]);
      }
    }

    const bool diag = (kt == qt);
    float tmx0 = -1e30f, tmx1 = -1e30f;
#pragma unroll
    for (int nf = 0; nf < 4; ++nf) {
#pragma unroll
      for (int j = 0; j < 4; ++j) {
        float sv = sa[nf][j] * scale;
        if (diag) {
          const int col = wn * 32 + nf * 8 + 2 * tq + (j & 1);
          const int rowl = row0 + ((j >= 2) ? 8 : 0);
          if (col > rowl) sv = -1e30f;
        }
        sa[nf][j] = sv;
        if (j < 2) tmx0 = fmaxf(tmx0, sv); else tmx1 = fmaxf(tmx1, sv);
      }
    }
    tmx0 = fmaxf(tmx0, __shfl_xor_sync(0xffffffffu, tmx0, 1));
    tmx0 = fmaxf(tmx0, __shfl_xor_sync(0xffffffffu, tmx0, 2));
    tmx1 = fmaxf(tmx1, __shfl_xor_sync(0xffffffffu, tmx1, 1));
    tmx1 = fmaxf(tmx1, __shfl_xor_sync(0xffffffffu, tmx1, 2));
    if (tq == 0) {
      redm[wn * 64 + row0] = tmx0;
      redm[wn * 64 + row0 + 8] = tmx1;
    }
    __syncthreads();   // barrier A

    const float fm0 = fmaxf(redm[row0], redm[64 + row0]);
    const float fm1 = fmaxf(redm[row0 + 8], redm[64 + row0 + 8]);
    const float mn0 = fmaxf(m0, fm0), mn1 = fmaxf(m1, fm1);
    const float al0 = __expf(m0 - mn0), al1 = __expf(m1 - mn1);
    m0 = mn0; m1 = mn1;

    float rs0 = 0.f, rs1 = 0.f;
#pragma unroll
    for (int nf = 0; nf < 4; ++nf) {
      float p0 = __expf(sa[nf][0] - mn0);
      float p1 = __expf(sa[nf][1] - mn0);
      float p2 = __expf(sa[nf][2] - mn1);
      float p3 = __expf(sa[nf][3] - mn1);
      rs0 += p0 + p1; rs1 += p2 + p3;
      sa[nf][0] = p0; sa[nf][1] = p1; sa[nf][2] = p2; sa[nf][3] = p3;
    }
    rs0 += __shfl_xor_sync(0xffffffffu, rs0, 1);
    rs0 += __shfl_xor_sync(0xffffffffu, rs0, 2);
    rs1 += __shfl_xor_sync(0xffffffffu, rs1, 1);
    rs1 += __shfl_xor_sync(0xffffffffu, rs1, 2);
    if (tq == 0) {
      reds[wn * 64 + row0] = rs0;
      reds[wn * 64 + row0 + 8] = rs1;
    }

#pragma unroll
    for (int nf = 0; nf < 8; ++nf) {
      oacc[nf][0] *= al0; oacc[nf][1] *= al0;
      oacc[nf][2] *= al1; oacc[nf][3] *= al1;
    }

#pragma unroll
    for (int nf = 0; nf < 4; ++nf) {
      const int pcol = wn * 32 + nf * 8 + 2 * tq;
      __nv_bfloat16 h0 = __float2bfloat16(sa[nf][0]);
      __nv_bfloat16 h1 = __float2bfloat16(sa[nf][1]);
      __nv_bfloat16 h2 = __float2bfloat16(sa[nf][2]);
      __nv_bfloat16 h3 = __float2bfloat16(sa[nf][3]);
      __nv_bfloat162 ph01; ph01.x = h0; ph01.y = h1;
      __nv_bfloat162 ph23; ph23.x = h2; ph23.y = h3;
      __nv_bfloat162 pl01, pl23;
      pl01.x = __float2bfloat16(sa[nf][0] - __bfloat162float(h0));
      pl01.y = __float2bfloat16(sa[nf][1] - __bfloat162float(h1));
      pl23.x = __float2bfloat16(sa[nf][2] - __bfloat162float(h2));
      pl23.y = __float2bfloat16(sa[nf][3] - __bfloat162float(h3));
      *(__nv_bfloat162*)(sb + SM_PH + row0 * LDP + pcol) = ph01;
      *(__nv_bfloat162*)(sb + SM_PH + (row0 + 8) * LDP + pcol) = ph23;
      *(__nv_bfloat162*)(sb + SM_PL + row0 * LDP + pcol) = pl01;
      *(__nv_bfloat162*)(sb + SM_PL + (row0 + 8) * LDP + pcol) = pl23;
    }
    cp_wait0();        // V ready (load overlapped S + softmax)
    __syncthreads();   // barrier B

    l0 = l0 * al0 + (reds[row0] + reds[64 + row0]);
    l1 = l1 * al1 + (reds[row0 + 8] + reds[64 + row0 + 8]);

#pragma unroll
    for (int k0i = 0; k0i < 64; k0i += 16) {
      uint32_t pah[4], pal[4];
      const uint32_t po = (uint32_t)((arow * LDP + k0i + kcol8) * 2);
      ldmx4(pah, sbase + SM_PH * 2 + po);
      ldmx4(pal, sbase + SM_PL * 2 + po);
#pragma unroll
      for (int df = 0; df < 4; ++df) {
        uint32_t th[4], tl[4];
        const uint32_t bo = (uint32_t)(((k0i + vrow) * LDK + wn * 64 + df * 16 + kcol8) * 2);
        ldmx4t(th, sbase + SM_VH * 2 + bo);
        ldmx4t(tl, sbase + SM_VL * 2 + bo);
        mma_bf16(oacc[df * 2],     pah, th[0], th[1]);
        mma_bf16(oacc[df * 2],     pah, tl[0], tl[1]);
        mma_bf16(oacc[df * 2],     pal, th[0], th[1]);
        mma_bf16(oacc[df * 2 + 1], pah, th[2], th[3]);
        mma_bf16(oacc[df * 2 + 1], pah, tl[2], tl[3]);
        mma_bf16(oacc[df * 2 + 1], pal, th[2], th[3]);
      }
    }
  }

  const float inv0 = 1.f / l0, inv1 = 1.f / l1;
  const size_t gr0 = (size_t)(b * Lr + q0 + row0) * HID_C;
  const size_t gr1 = gr0 + (size_t)8 * HID_C;
#pragma unroll
  for (int nf = 0; nf < 8; ++nf) {
    const int col = h * D_C + wn * 64 + nf * 8 + 2 * tq;
    float o0 = oacc[nf][0] * inv0, o1 = oacc[nf][1] * inv0;
    float o2 = oacc[nf][2] * inv1, o3 = oacc[nf][3] * inv1;
    __nv_bfloat162 h01, h23, l01, l23;
    h01.x = __float2bfloat16(o0); h01.y = __float2bfloat16(o1);
    h23.x = __float2bfloat16(o2); h23.y = __float2bfloat16(o3);
    l01.x = __float2bfloat16(o0 - __bfloat162float(h01.x));
    l01.y = __float2bfloat16(o1 - __bfloat162float(h01.y));
    l23.x = __float2bfloat16(o2 - __bfloat162float(h23.x));
    l23.y = __float2bfloat16(o3 - __bfloat162float(h23.y));
    *(__nv_bfloat162*)(Oh + gr0 + col) = h01;
    *(__nv_bfloat162*)(Oh + gr1 + col) = h23;
    *(__nv_bfloat162*)(Ol + gr0 + col) = l01;
    *(__nv_bfloat162*)(Ol + gr1 + col) = l23;
  }
}

// ---------------------------------------------------------------------------
// kernel_launch: x, cos, sin, wq, bq, wk, bk, wv, bv, wo
// ---------------------------------------------------------------------------
extern "C" void kernel_launch(void* const* d_in, const int* in_sizes, int n_in,
                              void* d_out, int out_size) {
  const float* x  = (const float*)d_in[0];
  const float* cs = (const float*)d_in[1];
  const float* sn = (const float*)d_in[2];
  const float* wq = (const float*)d_in[3];
  const float* bq = (const float*)d_in[4];
  const float* wk = (const float*)d_in[5];
  const float* bk = (const float*)d_in[6];
  const float* wv = (const float*)d_in[7];
  const float* bv = (const float*)d_in[8];
  const float* wo = (const float*)d_in[9];
  float* out = (float*)d_out;

  const int Lr = in_sizes[1] / 128;
  const int Mr = in_sizes[0] / HID_C;
  const int NKV = KV_C * D_C;

  void *qkvp, *bcp;
  void *xh, *xl, *wch, *wcl, *woh, *wol, *ah, *al;
  void *qhp, *qlp, *khp, *klp, *vhp, *vlp;
  cudaGetSymbolAddress(&qkvp, g_qkv);  cudaGetSymbolAddress(&bcp, g_bcat);
  cudaGetSymbolAddress(&xh, g_xh);     cudaGetSymbolAddress(&xl, g_xl);
  cudaGetSymbolAddress(&wch, g_wcath); cudaGetSymbolAddress(&wcl, g_wcatl);
  cudaGetSymbolAddress(&woh, g_woh);   cudaGetSymbolAddress(&wol, g_wol);
  cudaGetSymbolAddress(&ah, g_ah);     cudaGetSymbolAddress(&al, g_al);
  cudaGetSymbolAddress(&qhp, g_qh);    cudaGetSymbolAddress(&qlp, g_ql);
  cudaGetSymbolAddress(&khp, g_kh);    cudaGetSymbolAddress(&klp, g_kl);
  cudaGetSymbolAddress(&vhp, g_vh);    cudaGetSymbolAddress(&vlp, g_vl);

  cudaFuncSetAttribute(gemm_bf16x3<true>,  cudaFuncAttributeMaxDynamicSharedMemorySize, GEMM_SMEM);
  cudaFuncSetAttribute(gemm_bf16x3<false>, cudaFuncAttributeMaxDynamicSharedMemorySize, GEMM_SMEM);
  cudaFuncSetAttribute(flash_mma,          cudaFuncAttributeMaxDynamicSharedMemorySize, FLASH2_SMEM);

  dim3 blk(256);

  auto split = [&](const float* src, void* hi, void* lo, int n) {
    int n4 = n / 4;
    split_kernel<<<(n4 + 255) / 256, blk>>>(src, (__nv_bfloat16*)hi, (__nv_bfloat16*)lo, n4);
  };

  __nv_bfloat16* wcath = (__nv_bfloat16*)wch;
  __nv_bfloat16* wcatl = (__nv_bfloat16*)wcl;

  // splits of x and QKV weights (into concat buffer)
  split(x,  xh, xl, Mr * HID_C);
  split(wq, wcath,                          wcatl,                          HID_C * HID_C);
  split(wk, wcath + (size_t)HID_C * HID_C,  wcatl + (size_t)HID_C * HID_C,  NKV * HID_C);
  split(wv, wcath + (size_t)(HID_C + NKV) * HID_C,
            wcatl + (size_t)(HID_C + NKV) * HID_C, NKV * HID_C);
  bias_concat<<<(NCAT + 255) / 256, blk>>>(bq, bk, bv, (float*)bcp);

  // fused QKV projection (N=2560)
  dim3 gqkv(NCAT / 128, Mr / 128);
  gemm_bf16x3<true><<<gqkv, blk, GEMM_SMEM>>>(
      (const __nv_bfloat16*)xh, (const __nv_bfloat16*)xl,
      wcath, wcatl, (const float*)bcp, (float*)qkvp, Mr, NCAT, HID_C);

  // split wo
  split(wo, woh, wol, HID_C * HID_C);

  // RoPE + split q,k from fused buffer; split v from fused buffer
  const int rt = Mr * (H_C + KV_C) * 64;
  rope_split<<<(rt + 255) / 256, blk>>>((const float*)qkvp, cs, sn,
                                        (__nv_bfloat16*)qhp, (__nv_bfloat16*)qlp,
                                        (__nv_bfloat16*)khp, (__nv_bfloat16*)klp, Lr, Mr);
  {
    int n4 = Mr * 64;
    split_v_strided<<<(n4 + 255) / 256, blk>>>((const float*)qkvp,
                                               (__nv_bfloat16*)vhp, (__nv_bfloat16*)vlp, n4);
  }

  // Flash attention (writes bf16 hi/lo output)
  dim3 gf(Lr / 64, H_C, Mr / Lr);
  flash_mma<<<gf, blk, FLASH2_SMEM>>>(
      (const __nv_bfloat16*)qhp, (const __nv_bfloat16*)qlp,
      (const __nv_bfloat16*)khp, (const __nv_bfloat16*)klp,
      (const __nv_bfloat16*)vhp, (const __nv_bfloat16*)vlp,
      (__nv_bfloat16*)ah, (__nv_bfloat16*)al, Lr);

  // Output projection
  dim3 go(HID_C / 128, Mr / 128);
  gemm_bf16x3<false><<<go, blk, GEMM_SMEM>>>(
      (const __nv_bfloat16*)ah, (const __nv_bfloat16*)al,
      (const __nv_bfloat16*)woh, (const __nv_bfloat16*)wol,
      nullptr, out, Mr, HID_C, HID_C);
}

// round 13
// speedup vs baseline: 1.0752x; 1.0164x over previous
#include <cuda_runtime.h>
#include <cuda_bf16.h>
#include <cstdint>

// ---------------------------------------------------------------------------
// Problem constants
// ---------------------------------------------------------------------------
constexpr int HID_C = 2048;
constexpr int H_C   = 16;
constexpr int KV_C  = 2;
constexpr int D_C   = 128;
constexpr int MAXM  = 4096;
constexpr int NCAT  = HID_C + 2 * KV_C * D_C;   // 2560 fused QKV output cols

// ---------------------------------------------------------------------------
// Scratch (static __device__; no allocation anywhere)
// ---------------------------------------------------------------------------
__device__ float g_qkv[MAXM * NCAT];
__device__ float g_bcat[NCAT];

__device__ __nv_bfloat16 g_xh[MAXM * HID_C],  g_xl[MAXM * HID_C];
__device__ __nv_bfloat16 g_wcath[NCAT * HID_C], g_wcatl[NCAT * HID_C];
__device__ __nv_bfloat16 g_woh[HID_C * HID_C], g_wol[HID_C * HID_C];
__device__ __nv_bfloat16 g_ah[MAXM * HID_C],  g_al[MAXM * HID_C];

__device__ __nv_bfloat16 g_qh[MAXM * HID_C],       g_ql[MAXM * HID_C];
__device__ __nv_bfloat16 g_kh[MAXM * KV_C * D_C],  g_kl[MAXM * KV_C * D_C];
__device__ __nv_bfloat16 g_vh[MAXM * KV_C * D_C],  g_vl[MAXM * KV_C * D_C];

// ---------------------------------------------------------------------------
// Helpers
// ---------------------------------------------------------------------------
__device__ __forceinline__ uint32_t smem_u32(const void* p) {
  return (uint32_t)__cvta_generic_to_shared(p);
}
__device__ __forceinline__ void cp_async16(uint32_t dst, const void* src) {
  asm volatile("cp.async.cg.shared.global [%0], [%1], 16;" :: "r"(dst), "l"(src));
}
__device__ __forceinline__ void cp_commit() { asm volatile("cp.async.commit_group;"); }
__device__ __forceinline__ void cp_wait1()  { asm volatile("cp.async.wait_group 1;"); }
__device__ __forceinline__ void cp_wait0()  { asm volatile("cp.async.wait_group 0;"); }

__device__ __forceinline__ void ldmx4(uint32_t (&r)[4], uint32_t addr) {
  asm volatile("ldmatrix.sync.aligned.m8n8.x4.shared.b16 {%0,%1,%2,%3}, [%4];"
               : "=r"(r[0]), "=r"(r[1]), "=r"(r[2]), "=r"(r[3]) : "r"(addr));
}
__device__ __forceinline__ void ldmx4t(uint32_t (&r)[4], uint32_t addr) {
  asm volatile("ldmatrix.sync.aligned.m8n8.x4.trans.shared.b16 {%0,%1,%2,%3}, [%4];"
               : "=r"(r[0]), "=r"(r[1]), "=r"(r[2]), "=r"(r[3]) : "r"(addr));
}
__device__ __forceinline__ void mma_bf16(float (&d)[4], const uint32_t (&a)[4],
                                         const uint32_t b0, const uint32_t b1) {
  asm volatile(
      "mma.sync.aligned.m16n8k16.row.col.f32.bf16.bf16.f32 "
      "{%0,%1,%2,%3}, {%4,%5,%6,%7}, {%8,%9}, {%0,%1,%2,%3};"
      : "+f"(d[0]), "+f"(d[1]), "+f"(d[2]), "+f"(d[3])
      : "r"(a[0]), "r"(a[1]), "r"(a[2]), "r"(a[3]), "r"(b0), "r"(b1));
}

// ---------------------------------------------------------------------------
// Small kernels
// ---------------------------------------------------------------------------
__global__ void bias_concat(const float* __restrict__ bq, const float* __restrict__ bk,
                            const float* __restrict__ bv, float* __restrict__ bc) {
  int i = blockIdx.x * blockDim.x + threadIdx.x;
  if (i >= NCAT) return;
  float v;
  if (i < HID_C) v = bq[i];
  else if (i < HID_C + KV_C * D_C) v = bk[i - HID_C];
  else v = bv[i - HID_C - KV_C * D_C];
  bc[i] = v;
}

__global__ void split_kernel(const float* __restrict__ s, __nv_bfloat16* __restrict__ hi,
                             __nv_bfloat16* __restrict__ lo, int n4) {
  int i = blockIdx.x * blockDim.x + threadIdx.x;
  if (i >= n4) return;
  float4 v = ((const float4*)s)[i];
  __nv_bfloat16 h[4], l[4];
  float f[4] = {v.x, v.y, v.z, v.w};
#pragma unroll
  for (int j = 0; j < 4; ++j) {
    h[j] = __float2bfloat16(f[j]);
    l[j] = __float2bfloat16(f[j] - __bfloat162float(h[j]));
  }
  ((uint2*)hi)[i] = *(uint2*)h;
  ((uint2*)lo)[i] = *(uint2*)l;
}

__global__ void split_v_strided(const float* __restrict__ qkv,
                                __nv_bfloat16* __restrict__ hi,
                                __nv_bfloat16* __restrict__ lo, int n4) {
  int i = blockIdx.x * blockDim.x + threadIdx.x;
  if (i >= n4) return;
  int row = i >> 6, c4 = i & 63;
  float4 v = *(const float4*)(qkv + (size_t)row * NCAT + (HID_C + KV_C * D_C) + c4 * 4);
  __nv_bfloat16 h[4], l[4];
  float f[4] = {v.x, v.y, v.z, v.w};
#pragma unroll
  for (int j = 0; j < 4; ++j) {
    h[j] = __float2bfloat16(f[j]);
    l[j] = __float2bfloat16(f[j] - __bfloat162float(h[j]));
  }
  ((uint2*)hi)[i] = *(uint2*)h;
  ((uint2*)lo)[i] = *(uint2*)l;
}

// ---------------------------------------------------------------------------
// bf16x3 split-precision NT GEMM (tensor cores), occ 2 — proven R9
// ---------------------------------------------------------------------------
constexpr int LDAB = 40;
constexpr int GTILE = 128 * LDAB;
constexpr int GTILE_B = GTILE * 2;
constexpr int GEMM_SMEM = 8 * GTILE_B;

template <bool HAS_BIAS>
__global__ void __launch_bounds__(256, 2)
gemm_bf16x3(const __nv_bfloat16* __restrict__ Ah, const __nv_bfloat16* __restrict__ Al,
            const __nv_bfloat16* __restrict__ Bh, const __nv_bfloat16* __restrict__ Bl,
            const float* __restrict__ bias, float* __restrict__ C,
            int M, int N, int K) {
  extern __shared__ __nv_bfloat16 smb[];
  __nv_bfloat16* sAh = smb;
  __nv_bfloat16* sAl = smb + 2 * GTILE;
  __nv_bfloat16* sBh = smb + 4 * GTILE;
  __nv_bfloat16* sBl = smb + 6 * GTILE;

  const int tid = threadIdx.x;
  const int lane = tid & 31, wid = tid >> 5;
  const int wm = wid & 1, wn = wid >> 1;
  const int m0 = blockIdx.y * 128, n0 = blockIdx.x * 128;

  const int lrow = tid >> 2;
  const int lcol = (tid & 3) * 8;
  const size_t aoff = (size_t)(m0 + lrow) * K + lcol;
  const size_t boff = (size_t)(n0 + lrow) * K + lcol;
  const uint32_t sdst = (uint32_t)((lrow * LDAB + lcol) * 2);
  const uint32_t sAh0 = smem_u32(sAh) + sdst;
  const uint32_t sAl0 = smem_u32(sAl) + sdst;
  const uint32_t sBh0 = smem_u32(sBh) + sdst;
  const uint32_t sBl0 = smem_u32(sBl) + sdst;
  constexpr uint32_t RSTEP = 64 * LDAB * 2;

  const int KT = K / 32;

  auto load_tile = [&](int kt, int buf) {
    const size_t g = (size_t)kt * 32;
    const uint32_t so = (uint32_t)buf * GTILE_B;
    const size_t a2 = aoff + g, b2 = boff + g;
    cp_async16(sAh0 + so,         Ah + a2);
    cp_async16(sAh0 + so + RSTEP, Ah + a2 + (size_t)64 * K);
    cp_async16(sAl0 + so,         Al + a2);
    cp_async16(sAl0 + so + RSTEP, Al + a2 + (size_t)64 * K);
    cp_async16(sBh0 + so,         Bh + b2);
    cp_async16(sBh0 + so + RSTEP, Bh + b2 + (size_t)64 * K);
    cp_async16(sBl0 + so,         Bl + b2);
    cp_async16(sBl0 + so + RSTEP, Bl + b2 + (size_t)64 * K);
  };

  load_tile(0, 0);
  cp_commit();

  float acc[4][4][4];
#pragma unroll
  for (int i = 0; i < 4; ++i)
#pragma unroll
    for (int j = 0; j < 4; ++j)
#pragma unroll
      for (int r = 0; r < 4; ++r) acc[i][j][r] = 0.f;

  const int arow = wm * 64 + (lane & 15);
  const int acolx = ((lane >> 4) << 3);
  const int brow = wn * 32 + ((lane >> 4) << 3) + (lane & 7);
  const int bcolx = (((lane >> 3) & 1) << 3);
  const uint32_t sAhB = smem_u32(sAh), sAlB = smem_u32(sAl);
  const uint32_t sBhB = smem_u32(sBh), sBlB = smem_u32(sBl);

  for (int kt = 0; kt < KT; ++kt) {
    const int buf = kt & 1;
    if (kt + 1 < KT) {
      load_tile(kt + 1, buf ^ 1);
      cp_commit();
      cp_wait1();
    } else {
      cp_wait0();
    }
    __syncthreads();

    const uint32_t so = (uint32_t)buf * GTILE_B;
#pragma unroll
    for (int k2 = 0; k2 < 2; ++k2) {
      uint32_t afh[4][4], afl[4][4], bfh[4][2], bfl[4][2];
      const uint32_t acol = k2 * 16 + acolx;
      const uint32_t bcol = k2 * 16 + bcolx;
#pragma unroll
      for (int mt = 0; mt < 4; ++mt) {
        const uint32_t ao = so + (uint32_t)(((arow + mt * 16) * LDAB + acol) * 2);
        ldmx4(afh[mt], sAhB + ao);
        ldmx4(afl[mt], sAlB + ao);
      }
#pragma unroll
      for (int nt2 = 0; nt2 < 2; ++nt2) {
        uint32_t t[4];
        const uint32_t bo = so + (uint32_t)(((brow + nt2 * 16) * LDAB + bcol) * 2);
        ldmx4(t, sBhB + bo);
        bfh[nt2 * 2][0] = t[0]; bfh[nt2 * 2][1] = t[1];
        bfh[nt2 * 2 + 1][0] = t[2]; bfh[nt2 * 2 + 1][1] = t[3];
        ldmx4(t, sBlB + bo);
        bfl[nt2 * 2][0] = t[0]; bfl[nt2 * 2][1] = t[1];
        bfl[nt2 * 2 + 1][0] = t[2]; bfl[nt2 * 2 + 1][1] = t[3];
      }
#pragma unroll
      for (int mt = 0; mt < 4; ++mt)
#pragma unroll
        for (int nt = 0; nt < 4; ++nt) {
          mma_bf16(acc[mt][nt], afh[mt], bfh[nt][0], bfh[nt][1]);
          mma_bf16(acc[mt][nt], afh[mt], bfl[nt][0], bfl[nt][1]);
          mma_bf16(acc[mt][nt], afl[mt], bfh[nt][0], bfh[nt][1]);
        }
    }
    __syncthreads();
  }

  float2 bv[4];
#pragma unroll
  for (int nt = 0; nt < 4; ++nt) {
    const int col = n0 + wn * 32 + nt * 8 + (lane & 3) * 2;
    if (HAS_BIAS) { bv[nt].x = bias[col]; bv[nt].y = bias[col + 1]; }
    else          { bv[nt].x = 0.f;       bv[nt].y = 0.f; }
  }
#pragma unroll
  for (int mt = 0; mt < 4; ++mt) {
    const int r0 = m0 + wm * 64 + mt * 16 + (lane >> 2);
#pragma unroll
    for (int nt = 0; nt < 4; ++nt) {
      const int col = n0 + wn * 32 + nt * 8 + (lane & 3) * 2;
      float2 v0 = make_float2(acc[mt][nt][0] + bv[nt].x, acc[mt][nt][1] + bv[nt].y);
      float2 v1 = make_float2(acc[mt][nt][2] + bv[nt].x, acc[mt][nt][3] + bv[nt].y);
      *(float2*)(C + (size_t)r0 * N + col) = v0;
      *(float2*)(C + (size_t)(r0 + 8) * N + col) = v1;
    }
  }
}

// ---------------------------------------------------------------------------
// RoPE + bf16 hi/lo split (fused). Reads q,k from the fused QKV buffer.
// ---------------------------------------------------------------------------
__global__ void rope_split(const float* __restrict__ qkv,
                           const float* __restrict__ cs, const float* __restrict__ sn,
                           __nv_bfloat16* __restrict__ qh, __nv_bfloat16* __restrict__ ql,
                           __nv_bfloat16* __restrict__ kh, __nv_bfloat16* __restrict__ kl,
                           int Lr, int Mr) {
  const int per = (H_C + KV_C) * 64;
  int t = blockIdx.x * blockDim.x + threadIdx.x;
  if (t >= Mr * per) return;
  int row = t / per;
  int rem = t - row * per;
  int hd = rem >> 6;
  int d = rem & 63;
  int l = row % Lr;
  float c = cs[l * 128 + d];
  float s = sn[l * 128 + d];
  const float* p;
  __nv_bfloat16 *oh, *ol;
  if (hd < H_C) {
    p  = qkv + (size_t)row * NCAT + hd * D_C;
    size_t ob = (size_t)row * HID_C + hd * D_C;
    oh = qh + ob; ol = ql + ob;
  } else {
    p  = qkv + (size_t)row * NCAT + HID_C + (hd - H_C) * D_C;
    size_t ob = (size_t)row * (KV_C * D_C) + (hd - H_C) * D_C;
    oh = kh + ob; ol = kl + ob;
  }
  float x1 = p[d], x2 = p[d + 64];
  float y1 = x1 * c - x2 * s;
  float y2 = x2 * c + x1 * s;
  __nv_bfloat16 h1 = __float2bfloat16(y1);
  __nv_bfloat16 h2 = __float2bfloat16(y2);
  oh[d]      = h1;  ol[d]      = __float2bfloat16(y1 - __bfloat162float(h1));
  oh[d + 64] = h2;  ol[d + 64] = __float2bfloat16(y2 - __bfloat162float(h2));
}

// ---------------------------------------------------------------------------
// Flash attention, bf16x3 MMA, 64x64 tiles, 8 warps (4m x 2n), causal, GQA.
// V reuses the K smem tiles (loaded after barrier A) -> 89KB smem -> occ 2.
// B-fragment ldmatrix address uses bcol8 (bit 3 of lane) — the R10 bug fix.
// ---------------------------------------------------------------------------
constexpr int LDK = 136;
constexpr int LDP = 72;
constexpr int TILE_E = 64 * LDK;
constexpr int SM_QH = 0;
constexpr int SM_QL = TILE_E;
constexpr int SM_K1 = 2 * TILE_E;                 // K hi, then V hi
constexpr int SM_K2 = 3 * TILE_E;                 // K lo, then V lo
constexpr int SM_PH = 4 * TILE_E;
constexpr int SM_PL = 4 * TILE_E + 64 * LDP;
constexpr int SM_RED = 4 * TILE_E + 2 * 64 * LDP;
constexpr int FLASH4_SMEM = SM_RED * 2 + 2 * 128 * 4;   // 89088 bytes

__global__ void __launch_bounds__(256, 2)
flash_mma(const __nv_bfloat16* __restrict__ Qh, const __nv_bfloat16* __restrict__ Ql,
          const __nv_bfloat16* __restrict__ Kh, const __nv_bfloat16* __restrict__ Kl,
          const __nv_bfloat16* __restrict__ Vh, const __nv_bfloat16* __restrict__ Vl,
          __nv_bfloat16* __restrict__ Oh, __nv_bfloat16* __restrict__ Ol, int Lr) {
  extern __shared__ __nv_bfloat16 sb[];
  const uint32_t sbase = smem_u32(sb);
  float* redm = (float*)(sb + SM_RED);
  float* reds = redm + 128;

  const int qt = blockIdx.x, h = blockIdx.y, b = blockIdx.z;
  const int kvh = h >> 3;
  const int q0 = qt * 64;
  const int tid = threadIdx.x, lane = tid & 31, w = tid >> 5;
  const int wm = w & 3, wn = w >> 2;

  const int lr = tid & 63, lcg = tid >> 6;
  const uint32_t sd = (uint32_t)((lr * LDK + lcg * 32) * 2);

  // ---- Q tile (loaded once) ----
  {
    const size_t grow = (size_t)(b * Lr + q0 + lr) * HID_C + h * D_C + lcg * 32;
#pragma unroll
    for (int i = 0; i < 4; ++i) {
      cp_async16(sbase + SM_QH * 2 + sd + i * 16, Qh + grow + i * 8);
      cp_async16(sbase + SM_QL * 2 + sd + i * 16, Ql + grow + i * 8);
    }
    cp_commit();
  }

  const int rq = lane >> 2, tq = lane & 3;
  const int arow = wm * 16 + (lane & 15);
  const int kcol8 = (lane >> 4) << 3;
  const int brow = wn * 32 + kcol8 + (lane & 7);
  const int bcol8 = ((lane >> 3) & 1) << 3;
  const int vrow = lane & 15;
  const int row0 = wm * 16 + rq;

  float m0 = -1e30f, m1 = -1e30f, l0 = 0.f, l1 = 0.f;
  float oacc[8][4];
#pragma unroll
  for (int i = 0; i < 8; ++i)
#pragma unroll
    for (int j = 0; j < 4; ++j) oacc[i][j] = 0.f;

  const float scale = 0.08838834764831845f;
  const uint32_t K1B = sbase + SM_K1 * 2;
  const uint32_t K2B = sbase + SM_K2 * 2;

  for (int kt = 0; kt <= qt; ++kt) {
    const int k0 = kt * 64;
    const size_t gr = (size_t)(b * Lr + k0 + lr) * (KV_C * D_C) + kvh * D_C + lcg * 32;

    __syncthreads();   // previous iteration's PV reads of V complete
    // ---- load K into shared K/V tiles ----
#pragma unroll
    for (int i = 0; i < 4; ++i) {
      cp_async16(K1B + sd + i * 16, Kh + gr + i * 8);
      cp_async16(K2B + sd + i * 16, Kl + gr + i * 8);
    }
    cp_commit();
    cp_wait0();        // K (and Q on first iter) ready
    __syncthreads();

    // ---- S = Q K^T (3-term bf16x3) ----
    float sa[4][4];
#pragma unroll
    for (int i = 0; i < 4; ++i)
#pragma unroll
      for (int j = 0; j < 4; ++j) sa[i][j] = 0.f;

#pragma unroll
    for (int kst = 0; kst < 8; ++kst) {
      uint32_t ah4[4], al4[4];
      const uint32_t ao = (uint32_t)((arow * LDK + kst * 16 + kcol8) * 2);
      ldmx4(ah4, sbase + SM_QH * 2 + ao);
      ldmx4(al4, sbase + SM_QL * 2 + ao);
      uint32_t bh[4][2], bl[4][2];
#pragma unroll
      for (int nt2 = 0; nt2 < 2; ++nt2) {
        uint32_t t4[4];
        const uint32_t bo = (uint32_t)(((brow + nt2 * 16) * LDK + kst * 16 + bcol8) * 2);
        ldmx4(t4, K1B + bo);
        bh[nt2 * 2][0] = t4[0]; bh[nt2 * 2][1] = t4[1];
        bh[nt2 * 2 + 1][0] = t4[2]; bh[nt2 * 2 + 1][1] = t4[3];
        ldmx4(t4, K2B + bo);
        bl[nt2 * 2][0] = t4[0]; bl[nt2 * 2][1] = t4[1];
        bl[nt2 * 2 + 1][0] = t4[2]; bl[nt2 * 2 + 1][1] = t4[3];
      }
#pragma unroll
      for (int nf = 0; nf < 4; ++nf) {
        mma_bf16(sa[nf], ah4, bh[nf][0], bh[nf][1]);
        mma_bf16(sa[nf], ah4, bl[nf][0], bl[nf][1]);
        mma_bf16(sa[nf], al4, bh[nf][0], bh[nf][1]);
      }
    }

    // ---- scale + causal mask + partial row max ----
    const bool diag = (kt == qt);
    float tmx0 = -1e30f, tmx1 = -1e30f;
#pragma unroll
    for (int nf = 0; nf < 4; ++nf) {
#pragma unroll
      for (int j = 0; j < 4; ++j) {
        float sv = sa[nf][j] * scale;
        if (diag) {
          const int col = wn * 32 + nf * 8 + 2 * tq + (j & 1);
          const int rowl = row0 + ((j >= 2) ? 8 : 0);
          if (col > rowl) sv = -1e30f;
        }
        sa[nf][j] = sv;
        if (j < 2) tmx0 = fmaxf(tmx0, sv); else tmx1 = fmaxf(tmx1, sv);
      }
    }
    tmx0 = fmaxf(tmx0, __shfl_xor_sync(0xffffffffu, tmx0, 1));
    tmx0 = fmaxf(tmx0, __shfl_xor_sync(0xffffffffu, tmx0, 2));
    tmx1 = fmaxf(tmx1, __shfl_xor_sync(0xffffffffu, tmx1, 1));
    tmx1 = fmaxf(tmx1, __shfl_xor_sync(0xffffffffu, tmx1, 2));
    if (tq == 0) {
      redm[wn * 64 + row0] = tmx0;
      redm[wn * 64 + row0 + 8] = tmx1;
    }
    __syncthreads();   // barrier A: stats visible AND all K reads complete

    // ---- load V into the SAME tiles (overlaps softmax + P write) ----
#pragma unroll
    for (int i = 0; i < 4; ++i) {
      cp_async16(K1B + sd + i * 16, Vh + gr + i * 8);
      cp_async16(K2B + sd + i * 16, Vl + gr + i * 8);
    }
    cp_commit();

    // ---- full-row max -> online softmax update ----
    const float fm0 = fmaxf(redm[row0], redm[64 + row0]);
    const float fm1 = fmaxf(redm[row0 + 8], redm[64 + row0 + 8]);
    const float mn0 = fmaxf(m0, fm0), mn1 = fmaxf(m1, fm1);
    const float al0 = __expf(m0 - mn0), al1 = __expf(m1 - mn1);
    m0 = mn0; m1 = mn1;

    float rs0 = 0.f, rs1 = 0.f;
#pragma unroll
    for (int nf = 0; nf < 4; ++nf) {
      float p0 = __expf(sa[nf][0] - mn0);
      float p1 = __expf(sa[nf][1] - mn0);
      float p2 = __expf(sa[nf][2] - mn1);
      float p3 = __expf(sa[nf][3] - mn1);
      rs0 += p0 + p1; rs1 += p2 + p3;
      sa[nf][0] = p0; sa[nf][1] = p1; sa[nf][2] = p2; sa[nf][3] = p3;
    }
    rs0 += __shfl_xor_sync(0xffffffffu, rs0, 1);
    rs0 += __shfl_xor_sync(0xffffffffu, rs0, 2);
    rs1 += __shfl_xor_sync(0xffffffffu, rs1, 1);
    rs1 += __shfl_xor_sync(0xffffffffu, rs1, 2);
    if (tq == 0) {
      reds[wn * 64 + row0] = rs0;
      reds[wn * 64 + row0 + 8] = rs1;
    }

#pragma unroll
    for (int nf = 0; nf < 8; ++nf) {
      oacc[nf][0] *= al0; oacc[nf][1] *= al0;
      oacc[nf][2] *= al1; oacc[nf][3] *= al1;
    }

    // ---- write P (bf16 hi/lo) ----
#pragma unroll
    for (int nf = 0; nf < 4; ++nf) {
      const int pcol = wn * 32 + nf * 8 + 2 * tq;
      __nv_bfloat16 h0 = __float2bfloat16(sa[nf][0]);
      __nv_bfloat16 h1 = __float2bfloat16(sa[nf][1]);
      __nv_bfloat16 h2 = __float2bfloat16(sa[nf][2]);
      __nv_bfloat16 h3 = __float2bfloat16(sa[nf][3]);
      __nv_bfloat162 ph01; ph01.x = h0; ph01.y = h1;
      __nv_bfloat162 ph23; ph23.x = h2; ph23.y = h3;
      __nv_bfloat162 pl01, pl23;
      pl01.x = __float2bfloat16(sa[nf][0] - __bfloat162float(h0));
      pl01.y = __float2bfloat16(sa[nf][1] - __bfloat162float(h1));
      pl23.x = __float2bfloat16(sa[nf][2] - __bfloat162float(h2));
      pl23.y = __float2bfloat16(sa[nf][3] - __bfloat162float(h3));
      *(__nv_bfloat162*)(sb + SM_PH + row0 * LDP + pcol) = ph01;
      *(__nv_bfloat162*)(sb + SM_PH + (row0 + 8) * LDP + pcol) = ph23;
      *(__nv_bfloat162*)(sb + SM_PL + row0 * LDP + pcol) = pl01;
      *(__nv_bfloat162*)(sb + SM_PL + (row0 + 8) * LDP + pcol) = pl23;
    }
    cp_wait0();        // V resident
    __syncthreads();   // barrier B: P + sums + V visible

    l0 = l0 * al0 + (reds[row0] + reds[64 + row0]);
    l1 = l1 * al1 + (reds[row0 + 8] + reds[64 + row0 + 8]);

    // ---- O += P V (V fragments via ldmatrix.trans from reused tiles) ----
#pragma unroll
    for (int k0i = 0; k0i < 64; k0i += 16) {
      uint32_t pah[4], pal[4];
      const uint32_t po = (uint32_t)((arow * LDP + k0i + kcol8) * 2);
      ldmx4(pah, sbase + SM_PH * 2 + po);
      ldmx4(pal, sbase + SM_PL * 2 + po);
#pragma unroll
      for (int df = 0; df < 4; ++df) {
        uint32_t th[4], tl[4];
        const uint32_t bo = (uint32_t)(((k0i + vrow) * LDK + wn * 64 + df * 16 + kcol8) * 2);
        ldmx4t(th, K1B + bo);
        ldmx4t(tl, K2B + bo);
        mma_bf16(oacc[df * 2],     pah, th[0], th[1]);
        mma_bf16(oacc[df * 2],     pah, tl[0], tl[1]);
        mma_bf16(oacc[df * 2],     pal, th[0], th[1]);
        mma_bf16(oacc[df * 2 + 1], pah, th[2], th[3]);
        mma_bf16(oacc[df * 2 + 1], pah, tl[2], tl[3]);
        mma_bf16(oacc[df * 2 + 1], pal, th[2], th[3]);
      }
    }
  }

  // ---- normalize + write bf16 hi/lo output ----
  const float inv0 = 1.f / l0, inv1 = 1.f / l1;
  const size_t gr0 = (size_t)(b * Lr + q0 + row0) * HID_C;
  const size_t gr1 = gr0 + (size_t)8 * HID_C;
#pragma unroll
  for (int nf = 0; nf < 8; ++nf) {
    const int col = h * D_C + wn * 64 + nf * 8 + 2 * tq;
    float o0 = oacc[nf][0] * inv0, o1 = oacc[nf][1] * inv0;
    float o2 = oacc[nf][2] * inv1, o3 = oacc[nf][3] * inv1;
    __nv_bfloat162 h01, h23, l01, l23;
    h01.x = __float2bfloat16(o0); h01.y = __float2bfloat16(o1);
    h23.x = __float2bfloat16(o2); h23.y = __float2bfloat16(o3);
    l01.x = __float2bfloat16(o0 - __bfloat162float(h01.x));
    l01.y = __float2bfloat16(o1 - __bfloat162float(h01.y));
    l23.x = __float2bfloat16(o2 - __bfloat162float(h23.x));
    l23.y = __float2bfloat16(o3 - __bfloat162float(h23.y));
    *(__nv_bfloat162*)(Oh + gr0 + col) = h01;
    *(__nv_bfloat162*)(Oh + gr1 + col) = h23;
    *(__nv_bfloat162*)(Ol + gr0 + col) = l01;
    *(__nv_bfloat162*)(Ol + gr1 + col) = l23;
  }
}

// ---------------------------------------------------------------------------
// kernel_launch: x, cos, sin, wq, bq, wk, bk, wv, bv, wo
// ---------------------------------------------------------------------------
extern "C" void kernel_launch(void* const* d_in, const int* in_sizes, int n_in,
                              void* d_out, int out_size) {
  const float* x  = (const float*)d_in[0];
  const float* cs = (const float*)d_in[1];
  const float* sn = (const float*)d_in[2];
  const float* wq = (const float*)d_in[3];
  const float* bq = (const float*)d_in[4];
  const float* wk = (const float*)d_in[5];
  const float* bk = (const float*)d_in[6];
  const float* wv = (const float*)d_in[7];
  const float* bv = (const float*)d_in[8];
  const float* wo = (const float*)d_in[9];
  float* out = (float*)d_out;

  const int Lr = in_sizes[1] / 128;
  const int Mr = in_sizes[0] / HID_C;
  const int NKV = KV_C * D_C;

  void *qkvp, *bcp;
  void *xh, *xl, *wch, *wcl, *woh, *wol, *ah, *al;
  void *qhp, *qlp, *khp, *klp, *vhp, *vlp;
  cudaGetSymbolAddress(&qkvp, g_qkv);  cudaGetSymbolAddress(&bcp, g_bcat);
  cudaGetSymbolAddress(&xh, g_xh);     cudaGetSymbolAddress(&xl, g_xl);
  cudaGetSymbolAddress(&wch, g_wcath); cudaGetSymbolAddress(&wcl, g_wcatl);
  cudaGetSymbolAddress(&woh, g_woh);   cudaGetSymbolAddress(&wol, g_wol);
  cudaGetSymbolAddress(&ah, g_ah);     cudaGetSymbolAddress(&al, g_al);
  cudaGetSymbolAddress(&qhp, g_qh);    cudaGetSymbolAddress(&qlp, g_ql);
  cudaGetSymbolAddress(&khp, g_kh);    cudaGetSymbolAddress(&klp, g_kl);
  cudaGetSymbolAddress(&vhp, g_vh);    cudaGetSymbolAddress(&vlp, g_vl);

  cudaFuncSetAttribute(gemm_bf16x3<true>,  cudaFuncAttributeMaxDynamicSharedMemorySize, GEMM_SMEM);
  cudaFuncSetAttribute(gemm_bf16x3<false>, cudaFuncAttributeMaxDynamicSharedMemorySize, GEMM_SMEM);
  cudaFuncSetAttribute(flash_mma,          cudaFuncAttributeMaxDynamicSharedMemorySize, FLASH4_SMEM);

  dim3 blk(256);

  auto split = [&](const float* src, void* hi, void* lo, int n) {
    int n4 = n / 4;
    split_kernel<<<(n4 + 255) / 256, blk>>>(src, (__nv_bfloat16*)hi, (__nv_bfloat16*)lo, n4);
  };

  __nv_bfloat16* wcath = (__nv_bfloat16*)wch;
  __nv_bfloat16* wcatl = (__nv_bfloat16*)wcl;

  // splits of x and QKV weights (into concat buffer)
  split(x,  xh, xl, Mr * HID_C);
  split(wq, wcath,                          wcatl,                          HID_C * HID_C);
  split(wk, wcath + (size_t)HID_C * HID_C,  wcatl + (size_t)HID_C * HID_C,  NKV * HID_C);
  split(wv, wcath + (size_t)(HID_C + NKV) * HID_C,
            wcatl + (size_t)(HID_C + NKV) * HID_C, NKV * HID_C);
  bias_concat<<<(NCAT + 255) / 256, blk>>>(bq, bk, bv, (float*)bcp);

  // fused QKV projection (N=2560)
  dim3 gqkv(NCAT / 128, Mr / 128);
  gemm_bf16x3<true><<<gqkv, blk, GEMM_SMEM>>>(
      (const __nv_bfloat16*)xh, (const __nv_bfloat16*)xl,
      wcath, wcatl, (const float*)bcp, (float*)qkvp, Mr, NCAT, HID_C);

  // split wo
  split(wo, woh, wol, HID_C * HID_C);

  // RoPE + split q,k from fused buffer; split v from fused buffer
  const int rt = Mr * (H_C + KV_C) * 64;
  rope_split<<<(rt + 255) / 256, blk>>>((const float*)qkvp, cs, sn,
                                        (__nv_bfloat16*)qhp, (__nv_bfloat16*)qlp,
                                        (__nv_bfloat16*)khp, (__nv_bfloat16*)klp, Lr, Mr);
  {
    int n4 = Mr * 64;
    split_v_strided<<<(n4 + 255) / 256, blk>>>((const float*)qkvp,
                                               (__nv_bfloat16*)vhp, (__nv_bfloat16*)vlp, n4);
  }

  // Flash attention (occ 2, V reuses K tiles)
  dim3 gf(Lr / 64, H_C, Mr / Lr);
  flash_mma<<<gf, blk, FLASH4_SMEM>>>(
      (const __nv_bfloat16*)qhp, (const __nv_bfloat16*)qlp,
      (const __nv_bfloat16*)khp, (const __nv_bfloat16*)klp,
      (const __nv_bfloat16*)vhp, (const __nv_bfloat16*)vlp,
      (__nv_bfloat16*)ah, (__nv_bfloat16*)al, Lr);

  // Output projection
  dim3 go(HID_C / 128, Mr / 128);
  gemm_bf16x3<false><<<go, blk, GEMM_SMEM>>>(
      (const __nv_bfloat16*)ah, (const __nv_bfloat16*)al,
      (const __nv_bfloat16*)woh, (const __nv_bfloat16*)wol,
      nullptr, out, Mr, HID_C, HID_C);
}

// round 15
// speedup vs baseline: 1.1063x; 1.0290x over previous
#include <cuda_runtime.h>
#include <cuda_bf16.h>
#include <cstdint>

// ---------------------------------------------------------------------------
// Problem constants
// ---------------------------------------------------------------------------
constexpr int HID_C = 2048;
constexpr int H_C   = 16;
constexpr int KV_C  = 2;
constexpr int D_C   = 128;
constexpr int MAXM  = 4096;
constexpr int NCAT  = HID_C + 2 * KV_C * D_C;   // 2560 fused QKV output cols

// ---------------------------------------------------------------------------
// Scratch (static __device__; no allocation anywhere)
// ---------------------------------------------------------------------------
__device__ float g_qkv[MAXM * NCAT];
__device__ float g_bcat[NCAT];

__device__ __nv_bfloat16 g_xh[MAXM * HID_C],  g_xl[MAXM * HID_C];
__device__ __nv_bfloat16 g_wcath[NCAT * HID_C], g_wcatl[NCAT * HID_C];
__device__ __nv_bfloat16 g_woh[HID_C * HID_C], g_wol[HID_C * HID_C];
__device__ __nv_bfloat16 g_ah[MAXM * HID_C],  g_al[MAXM * HID_C];

__device__ __nv_bfloat16 g_qh[MAXM * HID_C],       g_ql[MAXM * HID_C];
__device__ __nv_bfloat16 g_kh[MAXM * KV_C * D_C],  g_kl[MAXM * KV_C * D_C];
__device__ __nv_bfloat16 g_vh[MAXM * KV_C * D_C],  g_vl[MAXM * KV_C * D_C];

// ---------------------------------------------------------------------------
// Helpers
// ---------------------------------------------------------------------------
__device__ __forceinline__ uint32_t smem_u32(const void* p) {
  return (uint32_t)__cvta_generic_to_shared(p);
}
__device__ __forceinline__ void cp_async16(uint32_t dst, const void* src) {
  asm volatile("cp.async.cg.shared.global [%0], [%1], 16;" :: "r"(dst), "l"(src));
}
__device__ __forceinline__ void cp_commit() { asm volatile("cp.async.commit_group;"); }
__device__ __forceinline__ void cp_wait0()  { asm volatile("cp.async.wait_group 0;"); }

__device__ __forceinline__ void ldmx4(uint32_t (&r)[4], uint32_t addr) {
  asm volatile("ldmatrix.sync.aligned.m8n8.x4.shared.b16 {%0,%1,%2,%3}, [%4];"
               : "=r"(r[0]), "=r"(r[1]), "=r"(r[2]), "=r"(r[3]) : "r"(addr));
}
__device__ __forceinline__ void ldmx4t(uint32_t (&r)[4], uint32_t addr) {
  asm volatile("ldmatrix.sync.aligned.m8n8.x4.trans.shared.b16 {%0,%1,%2,%3}, [%4];"
               : "=r"(r[0]), "=r"(r[1]), "=r"(r[2]), "=r"(r[3]) : "r"(addr));
}
__device__ __forceinline__ void mma_bf16(float (&d)[4], const uint32_t (&a)[4],
                                         const uint32_t b0, const uint32_t b1) {
  asm volatile(
      "mma.sync.aligned.m16n8k16.row.col.f32.bf16.bf16.f32 "
      "{%0,%1,%2,%3}, {%4,%5,%6,%7}, {%8,%9}, {%0,%1,%2,%3};"
      : "+f"(d[0]), "+f"(d[1]), "+f"(d[2]), "+f"(d[3])
      : "r"(a[0]), "r"(a[1]), "r"(a[2]), "r"(a[3]), "r"(b0), "r"(b1));
}

// ---------------------------------------------------------------------------
// Small kernels
// ---------------------------------------------------------------------------
__global__ void bias_concat(const float* __restrict__ bq, const float* __restrict__ bk,
                            const float* __restrict__ bv, float* __restrict__ bc) {
  int i = blockIdx.x * blockDim.x + threadIdx.x;
  if (i >= NCAT) return;
  float v;
  if (i < HID_C) v = bq[i];
  else if (i < HID_C + KV_C * D_C) v = bk[i - HID_C];
  else v = bv[i - HID_C - KV_C * D_C];
  bc[i] = v;
}

__global__ void split_kernel(const float* __restrict__ s, __nv_bfloat16* __restrict__ hi,
                             __nv_bfloat16* __restrict__ lo, int n4) {
  int i = blockIdx.x * blockDim.x + threadIdx.x;
  if (i >= n4) return;
  float4 v = ((const float4*)s)[i];
  __nv_bfloat16 h[4], l[4];
  float f[4] = {v.x, v.y, v.z, v.w};
#pragma unroll
  for (int j = 0; j < 4; ++j) {
    h[j] = __float2bfloat16(f[j]);
    l[j] = __float2bfloat16(f[j] - __bfloat162float(h[j]));
  }
  ((uint2*)hi)[i] = *(uint2*)h;
  ((uint2*)lo)[i] = *(uint2*)l;
}

__global__ void split_v_strided(const float* __restrict__ qkv,
                                __nv_bfloat16* __restrict__ hi,
                                __nv_bfloat16* __restrict__ lo, int n4) {
  int i = blockIdx.x * blockDim.x + threadIdx.x;
  if (i >= n4) return;
  int row = i >> 6, c4 = i & 63;
  float4 v = *(const float4*)(qkv + (size_t)row * NCAT + (HID_C + KV_C * D_C) + c4 * 4);
  __nv_bfloat16 h[4], l[4];
  float f[4] = {v.x, v.y, v.z, v.w};
#pragma unroll
  for (int j = 0; j < 4; ++j) {
    h[j] = __float2bfloat16(f[j]);
    l[j] = __float2bfloat16(f[j] - __bfloat162float(h[j]));
  }
  ((uint2*)hi)[i] = *(uint2*)h;
  ((uint2*)lo)[i] = *(uint2*)l;
}

// ---------------------------------------------------------------------------
// bf16x3 split-precision NT GEMM (tensor cores), occ 2.
// R15: single barrier per k-iter. Order: wait -> sync -> issue next load
// -> MMA. The one sync both publishes the landed tile and proves all reads
// of the buffer to be overwritten next have completed.
// ---------------------------------------------------------------------------
constexpr int LDAB = 40;
constexpr int GTILE = 128 * LDAB;
constexpr int GTILE_B = GTILE * 2;
constexpr int GEMM_SMEM = 8 * GTILE_B;

template <bool HAS_BIAS>
__global__ void __launch_bounds__(256, 2)
gemm_bf16x3(const __nv_bfloat16* __restrict__ Ah, const __nv_bfloat16* __restrict__ Al,
            const __nv_bfloat16* __restrict__ Bh, const __nv_bfloat16* __restrict__ Bl,
            const float* __restrict__ bias, float* __restrict__ C,
            int M, int N, int K) {
  extern __shared__ __nv_bfloat16 smb[];
  __nv_bfloat16* sAh = smb;
  __nv_bfloat16* sAl = smb + 2 * GTILE;
  __nv_bfloat16* sBh = smb + 4 * GTILE;
  __nv_bfloat16* sBl = smb + 6 * GTILE;

  const int tid = threadIdx.x;
  const int lane = tid & 31, wid = tid >> 5;
  const int wm = wid & 1, wn = wid >> 1;
  const int m0 = blockIdx.y * 128, n0 = blockIdx.x * 128;

  const int lrow = tid >> 2;
  const int lcol = (tid & 3) * 8;
  const size_t aoff = (size_t)(m0 + lrow) * K + lcol;
  const size_t boff = (size_t)(n0 + lrow) * K + lcol;
  const uint32_t sdst = (uint32_t)((lrow * LDAB + lcol) * 2);
  const uint32_t sAh0 = smem_u32(sAh) + sdst;
  const uint32_t sAl0 = smem_u32(sAl) + sdst;
  const uint32_t sBh0 = smem_u32(sBh) + sdst;
  const uint32_t sBl0 = smem_u32(sBl) + sdst;
  constexpr uint32_t RSTEP = 64 * LDAB * 2;

  const int KT = K / 32;

  auto load_tile = [&](int kt, int buf) {
    const size_t g = (size_t)kt * 32;
    const uint32_t so = (uint32_t)buf * GTILE_B;
    const size_t a2 = aoff + g, b2 = boff + g;
    cp_async16(sAh0 + so,         Ah + a2);
    cp_async16(sAh0 + so + RSTEP, Ah + a2 + (size_t)64 * K);
    cp_async16(sAl0 + so,         Al + a2);
    cp_async16(sAl0 + so + RSTEP, Al + a2 + (size_t)64 * K);
    cp_async16(sBh0 + so,         Bh + b2);
    cp_async16(sBh0 + so + RSTEP, Bh + b2 + (size_t)64 * K);
    cp_async16(sBl0 + so,         Bl + b2);
    cp_async16(sBl0 + so + RSTEP, Bl + b2 + (size_t)64 * K);
  };

  load_tile(0, 0);
  cp_commit();

  float acc[4][4][4];
#pragma unroll
  for (int i = 0; i < 4; ++i)
#pragma unroll
    for (int j = 0; j < 4; ++j)
#pragma unroll
      for (int r = 0; r < 4; ++r) acc[i][j][r] = 0.f;

  const int arow = wm * 64 + (lane & 15);
  const int acolx = ((lane >> 4) << 3);
  const int brow = wn * 32 + ((lane >> 4) << 3) + (lane & 7);
  const int bcolx = (((lane >> 3) & 1) << 3);
  const uint32_t sAhB = smem_u32(sAh), sAlB = smem_u32(sAl);
  const uint32_t sBhB = smem_u32(sBh), sBlB = smem_u32(sBl);

  for (int kt = 0; kt < KT; ++kt) {
    const int buf = kt & 1;
    cp_wait0();          // tile kt resident (this thread's copies)
    __syncthreads();     // all threads' copies visible; all reads of buf^1 done
    if (kt + 1 < KT) {
      load_tile(kt + 1, buf ^ 1);   // safe: nobody reads buf^1 this iter
      cp_commit();
    }

    const uint32_t so = (uint32_t)buf * GTILE_B;
#pragma unroll
    for (int k2 = 0; k2 < 2; ++k2) {
      uint32_t afh[4][4], afl[4][4], bfh[4][2], bfl[4][2];
      const uint32_t acol = k2 * 16 + acolx;
      const uint32_t bcol = k2 * 16 + bcolx;
#pragma unroll
      for (int mt = 0; mt < 4; ++mt) {
        const uint32_t ao = so + (uint32_t)(((arow + mt * 16) * LDAB + acol) * 2);
        ldmx4(afh[mt], sAhB + ao);
        ldmx4(afl[mt], sAlB + ao);
      }
#pragma unroll
      for (int nt2 = 0; nt2 < 2; ++nt2) {
        uint32_t t[4];
        const uint32_t bo = so + (uint32_t)(((brow + nt2 * 16) * LDAB + bcol) * 2);
        ldmx4(t, sBhB + bo);
        bfh[nt2 * 2][0] = t[0]; bfh[nt2 * 2][1] = t[1];
        bfh[nt2 * 2 + 1][0] = t[2]; bfh[nt2 * 2 + 1][1] = t[3];
        ldmx4(t, sBlB + bo);
        bfl[nt2 * 2][0] = t[0]; bfl[nt2 * 2][1] = t[1];
        bfl[nt2 * 2 + 1][0] = t[2]; bfl[nt2 * 2 + 1][1] = t[3];
      }
#pragma unroll
      for (int mt = 0; mt < 4; ++mt)
#pragma unroll
        for (int nt = 0; nt < 4; ++nt) {
          mma_bf16(acc[mt][nt], afh[mt], bfh[nt][0], bfh[nt][1]);
          mma_bf16(acc[mt][nt], afh[mt], bfl[nt][0], bfl[nt][1]);
          mma_bf16(acc[mt][nt], afl[mt], bfh[nt][0], bfh[nt][1]);
        }
    }
    // no end-of-iter barrier: next iter's sync (before its prefetch issue)
    // guarantees all reads of this buffer complete before it is overwritten.
  }

  float2 bv[4];
#pragma unroll
  for (int nt = 0; nt < 4; ++nt) {
    const int col = n0 + wn * 32 + nt * 8 + (lane & 3) * 2;
    if (HAS_BIAS) { bv[nt].x = bias[col]; bv[nt].y = bias[col + 1]; }
    else          { bv[nt].x = 0.f;       bv[nt].y = 0.f; }
  }
#pragma unroll
  for (int mt = 0; mt < 4; ++mt) {
    const int r0 = m0 + wm * 64 + mt * 16 + (lane >> 2);
#pragma unroll
    for (int nt = 0; nt < 4; ++nt) {
      const int col = n0 + wn * 32 + nt * 8 + (lane & 3) * 2;
      float2 v0 = make_float2(acc[mt][nt][0] + bv[nt].x, acc[mt][nt][1] + bv[nt].y);
      float2 v1 = make_float2(acc[mt][nt][2] + bv[nt].x, acc[mt][nt][3] + bv[nt].y);
      *(float2*)(C + (size_t)r0 * N + col) = v0;
      *(float2*)(C + (size_t)(r0 + 8) * N + col) = v1;
    }
  }
}

// ---------------------------------------------------------------------------
// RoPE + bf16 hi/lo split (fused). Reads q,k from the fused QKV buffer.
// ---------------------------------------------------------------------------
__global__ void rope_split(const float* __restrict__ qkv,
                           const float* __restrict__ cs, const float* __restrict__ sn,
                           __nv_bfloat16* __restrict__ qh, __nv_bfloat16* __restrict__ ql,
                           __nv_bfloat16* __restrict__ kh, __nv_bfloat16* __restrict__ kl,
                           int Lr, int Mr) {
  const int per = (H_C + KV_C) * 64;
  int t = blockIdx.x * blockDim.x + threadIdx.x;
  if (t >= Mr * per) return;
  int row = t / per;
  int rem = t - row * per;
  int hd = rem >> 6;
  int d = rem & 63;
  int l = row % Lr;
  float c = cs[l * 128 + d];
  float s = sn[l * 128 + d];
  const float* p;
  __nv_bfloat16 *oh, *ol;
  if (hd < H_C) {
    p  = qkv + (size_t)row * NCAT + hd * D_C;
    size_t ob = (size_t)row * HID_C + hd * D_C;
    oh = qh + ob; ol = ql + ob;
  } else {
    p  = qkv + (size_t)row * NCAT + HID_C + (hd - H_C) * D_C;
    size_t ob = (size_t)row * (KV_C * D_C) + (hd - H_C) * D_C;
    oh = kh + ob; ol = kl + ob;
  }
  float x1 = p[d], x2 = p[d + 64];
  float y1 = x1 * c - x2 * s;
  float y2 = x2 * c + x1 * s;
  __nv_bfloat16 h1 = __float2bfloat16(y1);
  __nv_bfloat16 h2 = __float2bfloat16(y2);
  oh[d]      = h1;  ol[d]      = __float2bfloat16(y1 - __bfloat162float(h1));
  oh[d + 64] = h2;  ol[d + 64] = __float2bfloat16(y2 - __bfloat162float(h2));
}

// ---------------------------------------------------------------------------
// Flash attention (R13 proven version): bf16x3 MMA, 64x64 tiles, occ 2,
// V reuses K smem tiles.
// ---------------------------------------------------------------------------
constexpr int LDK = 136;
constexpr int LDP = 72;
constexpr int TILE_E = 64 * LDK;
constexpr int SM_QH = 0;
constexpr int SM_QL = TILE_E;
constexpr int SM_K1 = 2 * TILE_E;
constexpr int SM_K2 = 3 * TILE_E;
constexpr int SM_PH = 4 * TILE_E;
constexpr int SM_PL = 4 * TILE_E + 64 * LDP;
constexpr int SM_RED = 4 * TILE_E + 2 * 64 * LDP;
constexpr int FLASH4_SMEM = SM_RED * 2 + 2 * 128 * 4;

__global__ void __launch_bounds__(256, 2)
flash_mma(const __nv_bfloat16* __restrict__ Qh, const __nv_bfloat16* __restrict__ Ql,
          const __nv_bfloat16* __restrict__ Kh, const __nv_bfloat16* __restrict__ Kl,
          const __nv_bfloat16* __restrict__ Vh, const __nv_bfloat16* __restrict__ Vl,
          __nv_bfloat16* __restrict__ Oh, __nv_bfloat16* __restrict__ Ol, int Lr) {
  extern __shared__ __nv_bfloat16 sb[];
  const uint32_t sbase = smem_u32(sb);
  float* redm = (float*)(sb + SM_RED);
  float* reds = redm + 128;

  const int qt = blockIdx.x, h = blockIdx.y, b = blockIdx.z;
  const int kvh = h >> 3;
  const int q0 = qt * 64;
  const int tid = threadIdx.x, lane = tid & 31, w = tid >> 5;
  const int wm = w & 3, wn = w >> 2;

  const int lr = tid & 63, lcg = tid >> 6;
  const uint32_t sd = (uint32_t)((lr * LDK + lcg * 32) * 2);

  {
    const size_t grow = (size_t)(b * Lr + q0 + lr) * HID_C + h * D_C + lcg * 32;
#pragma unroll
    for (int i = 0; i < 4; ++i) {
      cp_async16(sbase + SM_QH * 2 + sd + i * 16, Qh + grow + i * 8);
      cp_async16(sbase + SM_QL * 2 + sd + i * 16, Ql + grow + i * 8);
    }
    cp_commit();
  }

  const int rq = lane >> 2, tq = lane & 3;
  const int arow = wm * 16 + (lane & 15);
  const int kcol8 = (lane >> 4) << 3;
  const int brow = wn * 32 + kcol8 + (lane & 7);
  const int bcol8 = ((lane >> 3) & 1) << 3;
  const int vrow = lane & 15;
  const int row0 = wm * 16 + rq;

  float m0 = -1e30f, m1 = -1e30f, l0 = 0.f, l1 = 0.f;
  float oacc[8][4];
#pragma unroll
  for (int i = 0; i < 8; ++i)
#pragma unroll
    for (int j = 0; j < 4; ++j) oacc[i][j] = 0.f;

  const float scale = 0.08838834764831845f;
  const uint32_t K1B = sbase + SM_K1 * 2;
  const uint32_t K2B = sbase + SM_K2 * 2;

  for (int kt = 0; kt <= qt; ++kt) {
    const int k0 = kt * 64;
    const size_t gr = (size_t)(b * Lr + k0 + lr) * (KV_C * D_C) + kvh * D_C + lcg * 32;

    __syncthreads();
#pragma unroll
    for (int i = 0; i < 4; ++i) {
      cp_async16(K1B + sd + i * 16, Kh + gr + i * 8);
      cp_async16(K2B + sd + i * 16, Kl + gr + i * 8);
    }
    cp_commit();
    cp_wait0();
    __syncthreads();

    float sa[4][4];
#pragma unroll
    for (int i = 0; i < 4; ++i)
#pragma unroll
      for (int j = 0; j < 4; ++j) sa[i][j] = 0.f;

#pragma unroll
    for (int kst = 0; kst < 8; ++kst) {
      uint32_t ah4[4], al4[4];
      const uint32_t ao = (uint32_t)((arow * LDK + kst * 16 + kcol8) * 2);
      ldmx4(ah4, sbase + SM_QH * 2 + ao);
      ldmx4(al4, sbase + SM_QL * 2 + ao);
      uint32_t bh[4][2], bl[4][2];
#pragma unroll
      for (int nt2 = 0; nt2 < 2; ++nt2) {
        uint32_t t4[4];
        const uint32_t bo = (uint32_t)(((brow + nt2 * 16) * LDK + kst * 16 + bcol8) * 2);
        ldmx4(t4, K1B + bo);
        bh[nt2 * 2][0] = t4[0]; bh[nt2 * 2][1] = t4[1];
        bh[nt2 * 2 + 1][0] = t4[2]; bh[nt2 * 2 + 1][1] = t4[3];
        ldmx4(t4, K2B + bo);
        bl[nt2 * 2][0] = t4[0]; bl[nt2 * 2][1] = t4[1];
        bl[nt2 * 2 + 1][0] = t4[2]; bl[nt2 * 2 + 1][1] = t4[3];
      }
#pragma unroll
      for (int nf = 0; nf < 4; ++nf) {
        mma_bf16(sa[nf], ah4, bh[nf][0], bh[nf][1]);
        mma_bf16(sa[nf], ah4, bl[nf][0], bl[nf][1]);
        mma_bf16(sa[nf], al4, bh[nf][0], bh[nf][1]);
      }
    }

    const bool diag = (kt == qt);
    float tmx0 = -1e30f, tmx1 = -1e30f;
#pragma unroll
    for (int nf = 0; nf < 4; ++nf) {
#pragma unroll
      for (int j = 0; j < 4; ++j) {
        float sv = sa[nf][j] * scale;
        if (diag) {
          const int col = wn * 32 + nf * 8 + 2 * tq + (j & 1);
          const int rowl = row0 + ((j >= 2) ? 8 : 0);
          if (col > rowl) sv = -1e30f;
        }
        sa[nf][j] = sv;
        if (j < 2) tmx0 = fmaxf(tmx0, sv); else tmx1 = fmaxf(tmx1, sv);
      }
    }
    tmx0 = fmaxf(tmx0, __shfl_xor_sync(0xffffffffu, tmx0, 1));
    tmx0 = fmaxf(tmx0, __shfl_xor_sync(0xffffffffu, tmx0, 2));
    tmx1 = fmaxf(tmx1, __shfl_xor_sync(0xffffffffu, tmx1, 1));
    tmx1 = fmaxf(tmx1, __shfl_xor_sync(0xffffffffu, tmx1, 2));
    if (tq == 0) {
      redm[wn * 64 + row0] = tmx0;
      redm[wn * 64 + row0 + 8] = tmx1;
    }
    __syncthreads();   // barrier A

#pragma unroll
    for (int i = 0; i < 4; ++i) {
      cp_async16(K1B + sd + i * 16, Vh + gr + i * 8);
      cp_async16(K2B + sd + i * 16, Vl + gr + i * 8);
    }
    cp_commit();

    const float fm0 = fmaxf(redm[row0], redm[64 + row0]);
    const float fm1 = fmaxf(redm[row0 + 8], redm[64 + row0 + 8]);
    const float mn0 = fmaxf(m0, fm0), mn1 = fmaxf(m1, fm1);
    const float al0 = __expf(m0 - mn0), al1 = __expf(m1 - mn1);
    m0 = mn0; m1 = mn1;

    float rs0 = 0.f, rs1 = 0.f;
#pragma unroll
    for (int nf = 0; nf < 4; ++nf) {
      float p0 = __expf(sa[nf][0] - mn0);
      float p1 = __expf(sa[nf][1] - mn0);
      float p2 = __expf(sa[nf][2] - mn1);
      float p3 = __expf(sa[nf][3] - mn1);
      rs0 += p0 + p1; rs1 += p2 + p3;
      sa[nf][0] = p0; sa[nf][1] = p1; sa[nf][2] = p2; sa[nf][3] = p3;
    }
    rs0 += __shfl_xor_sync(0xffffffffu, rs0, 1);
    rs0 += __shfl_xor_sync(0xffffffffu, rs0, 2);
    rs1 += __shfl_xor_sync(0xffffffffu, rs1, 1);
    rs1 += __shfl_xor_sync(0xffffffffu, rs1, 2);
    if (tq == 0) {
      reds[wn * 64 + row0] = rs0;
      reds[wn * 64 + row0 + 8] = rs1;
    }

#pragma unroll
    for (int nf = 0; nf < 8; ++nf) {
      oacc[nf][0] *= al0; oacc[nf][1] *= al0;
      oacc[nf][2] *= al1; oacc[nf][3] *= al1;
    }

#pragma unroll
    for (int nf = 0; nf < 4; ++nf) {
      const int pcol = wn * 32 + nf * 8 + 2 * tq;
      __nv_bfloat16 h0 = __float2bfloat16(sa[nf][0]);
      __nv_bfloat16 h1 = __float2bfloat16(sa[nf][1]);
      __nv_bfloat16 h2 = __float2bfloat16(sa[nf][2]);
      __nv_bfloat16 h3 = __float2bfloat16(sa[nf][3]);
      __nv_bfloat162 ph01; ph01.x = h0; ph01.y = h1;
      __nv_bfloat162 ph23; ph23.x = h2; ph23.y = h3;
      __nv_bfloat162 pl01, pl23;
      pl01.x = __float2bfloat16(sa[nf][0] - __bfloat162float(h0));
      pl01.y = __float2bfloat16(sa[nf][1] - __bfloat162float(h1));
      pl23.x = __float2bfloat16(sa[nf][2] - __bfloat162float(h2));
      pl23.y = __float2bfloat16(sa[nf][3] - __bfloat162float(h3));
      *(__nv_bfloat162*)(sb + SM_PH + row0 * LDP + pcol) = ph01;
      *(__nv_bfloat162*)(sb + SM_PH + (row0 + 8) * LDP + pcol) = ph23;
      *(__nv_bfloat162*)(sb + SM_PL + row0 * LDP + pcol) = pl01;
      *(__nv_bfloat162*)(sb + SM_PL + (row0 + 8) * LDP + pcol) = pl23;
    }
    cp_wait0();
    __syncthreads();   // barrier B

    l0 = l0 * al0 + (reds[row0] + reds[64 + row0]);
    l1 = l1 * al1 + (reds[row0 + 8] + reds[64 + row0 + 8]);

#pragma unroll
    for (int k0i = 0; k0i < 64; k0i += 16) {
      uint32_t pah[4], pal[4];
      const uint32_t po = (uint32_t)((arow * LDP + k0i + kcol8) * 2);
      ldmx4(pah, sbase + SM_PH * 2 + po);
      ldmx4(pal, sbase + SM_PL * 2 + po);
#pragma unroll
      for (int df = 0; df < 4; ++df) {
        uint32_t th[4], tl[4];
        const uint32_t bo = (uint32_t)(((k0i + vrow) * LDK + wn * 64 + df * 16 + kcol8) * 2);
        ldmx4t(th, K1B + bo);
        ldmx4t(tl, K2B + bo);
        mma_bf16(oacc[df * 2],     pah, th[0], th[1]);
        mma_bf16(oacc[df * 2],     pah, tl[0], tl[1]);
        mma_bf16(oacc[df * 2],     pal, th[0], th[1]);
        mma_bf16(oacc[df * 2 + 1], pah, th[2], th[3]);
        mma_bf16(oacc[df * 2 + 1], pah, tl[2], tl[3]);
        mma_bf16(oacc[df * 2 + 1], pal, th[2], th[3]);
      }
    }
  }

  const float inv0 = 1.f / l0, inv1 = 1.f / l1;
  const size_t gr0 = (size_t)(b * Lr + q0 + row0) * HID_C;
  const size_t gr1 = gr0 + (size_t)8 * HID_C;
#pragma unroll
  for (int nf = 0; nf < 8; ++nf) {
    const int col = h * D_C + wn * 64 + nf * 8 + 2 * tq;
    float o0 = oacc[nf][0] * inv0, o1 = oacc[nf][1] * inv0;
    float o2 = oacc[nf][2] * inv1, o3 = oacc[nf][3] * inv1;
    __nv_bfloat162 h01, h23, l01, l23;
    h01.x = __float2bfloat16(o0); h01.y = __float2bfloat16(o1);
    h23.x = __float2bfloat16(o2); h23.y = __float2bfloat16(o3);
    l01.x = __float2bfloat16(o0 - __bfloat162float(h01.x));
    l01.y = __float2bfloat16(o1 - __bfloat162float(h01.y));
    l23.x = __float2bfloat16(o2 - __bfloat162float(h23.x));
    l23.y = __float2bfloat16(o3 - __bfloat162float(h23.y));
    *(__nv_bfloat162*)(Oh + gr0 + col) = h01;
    *(__nv_bfloat162*)(Oh + gr1 + col) = h23;
    *(__nv_bfloat162*)(Ol + gr0 + col) = l01;
    *(__nv_bfloat162*)(Ol + gr1 + col) = l23;
  }
}

// ---------------------------------------------------------------------------
// kernel_launch: x, cos, sin, wq, bq, wk, bk, wv, bv, wo
// ---------------------------------------------------------------------------
extern "C" void kernel_launch(void* const* d_in, const int* in_sizes, int n_in,
                              void* d_out, int out_size) {
  const float* x  = (const float*)d_in[0];
  const float* cs = (const float*)d_in[1];
  const float* sn = (const float*)d_in[2];
  const float* wq = (const float*)d_in[3];
  const float* bq = (const float*)d_in[4];
  const float* wk = (const float*)d_in[5];
  const float* bk = (const float*)d_in[6];
  const float* wv = (const float*)d_in[7];
  const float* bv = (const float*)d_in[8];
  const float* wo = (const float*)d_in[9];
  float* out = (float*)d_out;

  const int Lr = in_sizes[1] / 128;
  const int Mr = in_sizes[0] / HID_C;
  const int NKV = KV_C * D_C;

  void *qkvp, *bcp;
  void *xh, *xl, *wch, *wcl, *woh, *wol, *ah, *al;
  void *qhp, *qlp, *khp, *klp, *vhp, *vlp;
  cudaGetSymbolAddress(&qkvp, g_qkv);  cudaGetSymbolAddress(&bcp, g_bcat);
  cudaGetSymbolAddress(&xh, g_xh);     cudaGetSymbolAddress(&xl, g_xl);
  cudaGetSymbolAddress(&wch, g_wcath); cudaGetSymbolAddress(&wcl, g_wcatl);
  cudaGetSymbolAddress(&woh, g_woh);   cudaGetSymbolAddress(&wol, g_wol);
  cudaGetSymbolAddress(&ah, g_ah);     cudaGetSymbolAddress(&al, g_al);
  cudaGetSymbolAddress(&qhp, g_qh);    cudaGetSymbolAddress(&qlp, g_ql);
  cudaGetSymbolAddress(&khp, g_kh);    cudaGetSymbolAddress(&klp, g_kl);
  cudaGetSymbolAddress(&vhp, g_vh);    cudaGetSymbolAddress(&vlp, g_vl);

  cudaFuncSetAttribute(gemm_bf16x3<true>,  cudaFuncAttributeMaxDynamicSharedMemorySize, GEMM_SMEM);
  cudaFuncSetAttribute(gemm_bf16x3<false>, cudaFuncAttributeMaxDynamicSharedMemorySize, GEMM_SMEM);
  cudaFuncSetAttribute(flash_mma,          cudaFuncAttributeMaxDynamicSharedMemorySize, FLASH4_SMEM);

  dim3 blk(256);

  auto split = [&](const float* src, void* hi, void* lo, int n) {
    int n4 = n / 4;
    split_kernel<<<(n4 + 255) / 256, blk>>>(src, (__nv_bfloat16*)hi, (__nv_bfloat16*)lo, n4);
  };

  __nv_bfloat16* wcath = (__nv_bfloat16*)wch;
  __nv_bfloat16* wcatl = (__nv_bfloat16*)wcl;

  split(x,  xh, xl, Mr * HID_C);
  split(wq, wcath,                          wcatl,                          HID_C * HID_C);
  split(wk, wcath + (size_t)HID_C * HID_C,  wcatl + (size_t)HID_C * HID_C,  NKV * HID_C);
  split(wv, wcath + (size_t)(HID_C + NKV) * HID_C,
            wcatl + (size_t)(HID_C + NKV) * HID_C, NKV * HID_C);
  bias_concat<<<(NCAT + 255) / 256, blk>>>(bq, bk, bv, (float*)bcp);

  // fused QKV projection (N=2560)
  dim3 gqkv(NCAT / 128, Mr / 128);
  gemm_bf16x3<true><<<gqkv, blk, GEMM_SMEM>>>(
      (const __nv_bfloat16*)xh, (const __nv_bfloat16*)xl,
      wcath, wcatl, (const float*)bcp, (float*)qkvp, Mr, NCAT, HID_C);

  split(wo, woh, wol, HID_C * HID_C);

  const int rt = Mr * (H_C + KV_C) * 64;
  rope_split<<<(rt + 255) / 256, blk>>>((const float*)qkvp, cs, sn,
                                        (__nv_bfloat16*)qhp, (__nv_bfloat16*)qlp,
                                        (__nv_bfloat16*)khp, (__nv_bfloat16*)klp, Lr, Mr);
  {
    int n4 = Mr * 64;
    split_v_strided<<<(n4 + 255) / 256, blk>>>((const float*)qkvp,
                                               (__nv_bfloat16*)vhp, (__nv_bfloat16*)vlp, n4);
  }

  dim3 gf(Lr / 64, H_C, Mr / Lr);
  flash_mma<<<gf, blk, FLASH4_SMEM>>>(
      (const __nv_bfloat16*)qhp, (const __nv_bfloat16*)qlp,
      (const __nv_bfloat16*)khp, (const __nv_bfloat16*)klp,
      (const __nv_bfloat16*)vhp, (const __nv_bfloat16*)vlp,
      (__nv_bfloat16*)ah, (__nv_bfloat16*)al, Lr);

  dim3 go(HID_C / 128, Mr / 128);
  gemm_bf16x3<false><<<go, blk, GEMM_SMEM>>>(
      (const __nv_bfloat16*)ah, (const __nv_bfloat16*)al,
      (const __nv_bfloat16*)woh, (const __nv_bfloat16*)wol,
      nullptr, out, Mr, HID_C, HID_C);
}

// round 16
// speedup vs baseline: 1.1173x; 1.0099x over previous
#include <cuda_runtime.h>
#include <cuda_bf16.h>
#include <cstdint>

// ---------------------------------------------------------------------------
// Problem constants
// ---------------------------------------------------------------------------
constexpr int HID_C = 2048;
constexpr int H_C   = 16;
constexpr int KV_C  = 2;
constexpr int D_C   = 128;
constexpr int MAXM  = 4096;
constexpr int NCAT  = HID_C + 2 * KV_C * D_C;   // 2560 fused QKV output cols
constexpr int NKVC  = KV_C * D_C;               // 256

// ---------------------------------------------------------------------------
// Scratch (static __device__; no allocation anywhere)
// ---------------------------------------------------------------------------
__device__ float g_qkv[MAXM * NCAT];
__device__ float g_bcat[NCAT];

__device__ __nv_bfloat16 g_xh[MAXM * HID_C],  g_xl[MAXM * HID_C];
__device__ __nv_bfloat16 g_wcath[NCAT * HID_C], g_wcatl[NCAT * HID_C];
__device__ __nv_bfloat16 g_woh[HID_C * HID_C], g_wol[HID_C * HID_C];
__device__ __nv_bfloat16 g_ah[MAXM * HID_C],  g_al[MAXM * HID_C];

__device__ __nv_bfloat16 g_qh[MAXM * HID_C],       g_ql[MAXM * HID_C];
__device__ __nv_bfloat16 g_kh[MAXM * NKVC],  g_kl[MAXM * NKVC];
__device__ __nv_bfloat16 g_vh[MAXM * NKVC],  g_vl[MAXM * NKVC];

// ---------------------------------------------------------------------------
// Helpers
// ---------------------------------------------------------------------------
__device__ __forceinline__ uint32_t smem_u32(const void* p) {
  return (uint32_t)__cvta_generic_to_shared(p);
}
__device__ __forceinline__ void cp_async16(uint32_t dst, const void* src) {
  asm volatile("cp.async.cg.shared.global [%0], [%1], 16;" :: "r"(dst), "l"(src));
}
__device__ __forceinline__ void cp_commit() { asm volatile("cp.async.commit_group;"); }
__device__ __forceinline__ void cp_wait0()  { asm volatile("cp.async.wait_group 0;"); }

__device__ __forceinline__ void ldmx4(uint32_t (&r)[4], uint32_t addr) {
  asm volatile("ldmatrix.sync.aligned.m8n8.x4.shared.b16 {%0,%1,%2,%3}, [%4];"
               : "=r"(r[0]), "=r"(r[1]), "=r"(r[2]), "=r"(r[3]) : "r"(addr));
}
__device__ __forceinline__ void ldmx4t(uint32_t (&r)[4], uint32_t addr) {
  asm volatile("ldmatrix.sync.aligned.m8n8.x4.trans.shared.b16 {%0,%1,%2,%3}, [%4];"
               : "=r"(r[0]), "=r"(r[1]), "=r"(r[2]), "=r"(r[3]) : "r"(addr));
}
__device__ __forceinline__ void mma_bf16(float (&d)[4], const uint32_t (&a)[4],
                                         const uint32_t b0, const uint32_t b1) {
  asm volatile(
      "mma.sync.aligned.m16n8k16.row.col.f32.bf16.bf16.f32 "
      "{%0,%1,%2,%3}, {%4,%5,%6,%7}, {%8,%9}, {%0,%1,%2,%3};"
      : "+f"(d[0]), "+f"(d[1]), "+f"(d[2]), "+f"(d[3])
      : "r"(a[0]), "r"(a[1]), "r"(a[2]), "r"(a[3]), "r"(b0), "r"(b1));
}

__device__ __forceinline__ void split4_store(const float4 v,
                                             __nv_bfloat16* hi, __nv_bfloat16* lo,
                                             size_t j) {
  __nv_bfloat16 h[4], l[4];
  float f[4] = {v.x, v.y, v.z, v.w};
#pragma unroll
  for (int t = 0; t < 4; ++t) {
    h[t] = __float2bfloat16(f[t]);
    l[t] = __float2bfloat16(f[t] - __bfloat162float(h[t]));
  }
  ((uint2*)hi)[j] = *(uint2*)h;
  ((uint2*)lo)[j] = *(uint2*)l;
}

// ---------------------------------------------------------------------------
// prep_all: fused splits of x, wq, wk, wv, wo (+ bias concat). One launch.
// Region map (in float4 units): [x | wq | wk | wv | wo | bias]
// ---------------------------------------------------------------------------
__global__ void prep_all(const float* __restrict__ x,
                         const float* __restrict__ wq, const float* __restrict__ wk,
                         const float* __restrict__ wv, const float* __restrict__ wo,
                         const float* __restrict__ bq, const float* __restrict__ bk,
                         const float* __restrict__ bv,
                         __nv_bfloat16* __restrict__ xh, __nv_bfloat16* __restrict__ xl,
                         __nv_bfloat16* __restrict__ wch, __nv_bfloat16* __restrict__ wcl,
                         __nv_bfloat16* __restrict__ woh, __nv_bfloat16* __restrict__ wol,
                         float* __restrict__ bc, int n_x4) {
  const int i = blockIdx.x * blockDim.x + threadIdx.x;
  const int R0 = n_x4;                          // end of x
  const int R1 = R0 + (HID_C * HID_C / 4);      // end of wq
  const int R2 = R1 + (NKVC * HID_C / 4);       // end of wk
  const int R3 = R2 + (NKVC * HID_C / 4);       // end of wv
  const int R4 = R3 + (HID_C * HID_C / 4);      // end of wo
  const int R5 = R4 + (NCAT / 4);               // end of bias
  if (i >= R5) return;

  if (i < R4) {
    const float* src;
    __nv_bfloat16 *hi, *lo;
    size_t j;
    if (i < R0)      { src = x;  hi = xh;  lo = xl;  j = i; }
    else if (i < R1) { src = wq; hi = wch; lo = wcl; j = i - R0; }
    else if (i < R2) { src = wk; j = i - R1;
                       hi = wch + (size_t)HID_C * HID_C;
                       lo = wcl + (size_t)HID_C * HID_C; }
    else if (i < R3) { src = wv; j = i - R2;
                       hi = wch + (size_t)(HID_C + NKVC) * HID_C;
                       lo = wcl + (size_t)(HID_C + NKVC) * HID_C; }
    else             { src = wo; hi = woh; lo = wol; j = i - R3; }
    split4_store(((const float4*)src)[j], hi, lo, j);
  } else {
    const int base = (i - R4) * 4;
#pragma unroll
    for (int t = 0; t < 4; ++t) {
      const int idx = base + t;
      float v;
      if (idx < HID_C) v = bq[idx];
      else if (idx < HID_C + NKVC) v = bk[idx - HID_C];
      else v = bv[idx - HID_C - NKVC];
      bc[idx] = v;
    }
  }
}

// ---------------------------------------------------------------------------
// rope_split_v: RoPE+split for q,k AND plain split for v, one pass over the
// fused QKV buffer. hd 0-15: q heads (rope), 16-17: k heads (rope),
// 18-19: v heads (no rotation).
// ---------------------------------------------------------------------------
__global__ void rope_split_v(const float* __restrict__ qkv,
                             const float* __restrict__ cs, const float* __restrict__ sn,
                             __nv_bfloat16* __restrict__ qh, __nv_bfloat16* __restrict__ ql,
                             __nv_bfloat16* __restrict__ kh, __nv_bfloat16* __restrict__ kl,
                             __nv_bfloat16* __restrict__ vh, __nv_bfloat16* __restrict__ vl,
                             int Lr, int Mr) {
  const int per = (H_C + 2 * KV_C) * 64;   // 20*64 = 1280
  int t = blockIdx.x * blockDim.x + threadIdx.x;
  if (t >= Mr * per) return;
  int row = t / per;
  int rem = t - row * per;
  int hd = rem >> 6;
  int d = rem & 63;

  const float* p;
  __nv_bfloat16 *oh, *ol;
  float c = 1.f, s = 0.f;
  bool rot = true;
  if (hd < H_C) {
    p  = qkv + (size_t)row * NCAT + hd * D_C;
    size_t ob = (size_t)row * HID_C + hd * D_C;
    oh = qh + ob; ol = ql + ob;
  } else if (hd < H_C + KV_C) {
    p  = qkv + (size_t)row * NCAT + HID_C + (hd - H_C) * D_C;
    size_t ob = (size_t)row * NKVC + (hd - H_C) * D_C;
    oh = kh + ob; ol = kl + ob;
  } else {
    const int hv = hd - H_C - KV_C;
    p  = qkv + (size_t)row * NCAT + HID_C + NKVC + hv * D_C;
    size_t ob = (size_t)row * NKVC + hv * D_C;
    oh = vh + ob; ol = vl + ob;
    rot = false;
  }
  if (rot) {
    const int l = row % Lr;
    c = cs[l * 128 + d];
    s = sn[l * 128 + d];
  }
  float x1 = p[d], x2 = p[d + 64];
  float y1 = rot ? (x1 * c - x2 * s) : x1;
  float y2 = rot ? (x2 * c + x1 * s) : x2;
  __nv_bfloat16 h1 = __float2bfloat16(y1);
  __nv_bfloat16 h2 = __float2bfloat16(y2);
  oh[d]      = h1;  ol[d]      = __float2bfloat16(y1 - __bfloat162float(h1));
  oh[d + 64] = h2;  ol[d + 64] = __float2bfloat16(y2 - __bfloat162float(h2));
}

// ---------------------------------------------------------------------------
// bf16x3 split-precision NT GEMM (tensor cores), occ 2, single barrier per
// k-iter (R15 proven): wait -> sync -> issue next load -> MMA.
// ---------------------------------------------------------------------------
constexpr int LDAB = 40;
constexpr int GTILE = 128 * LDAB;
constexpr int GTILE_B = GTILE * 2;
constexpr int GEMM_SMEM = 8 * GTILE_B;

template <bool HAS_BIAS>
__global__ void __launch_bounds__(256, 2)
gemm_bf16x3(const __nv_bfloat16* __restrict__ Ah, const __nv_bfloat16* __restrict__ Al,
            const __nv_bfloat16* __restrict__ Bh, const __nv_bfloat16* __restrict__ Bl,
            const float* __restrict__ bias, float* __restrict__ C,
            int M, int N, int K) {
  extern __shared__ __nv_bfloat16 smb[];
  __nv_bfloat16* sAh = smb;
  __nv_bfloat16* sAl = smb + 2 * GTILE;
  __nv_bfloat16* sBh = smb + 4 * GTILE;
  __nv_bfloat16* sBl = smb + 6 * GTILE;

  const int tid = threadIdx.x;
  const int lane = tid & 31, wid = tid >> 5;
  const int wm = wid & 1, wn = wid >> 1;
  const int m0 = blockIdx.y * 128, n0 = blockIdx.x * 128;

  const int lrow = tid >> 2;
  const int lcol = (tid & 3) * 8;
  const size_t aoff = (size_t)(m0 + lrow) * K + lcol;
  const size_t boff = (size_t)(n0 + lrow) * K + lcol;
  const uint32_t sdst = (uint32_t)((lrow * LDAB + lcol) * 2);
  const uint32_t sAh0 = smem_u32(sAh) + sdst;
  const uint32_t sAl0 = smem_u32(sAl) + sdst;
  const uint32_t sBh0 = smem_u32(sBh) + sdst;
  const uint32_t sBl0 = smem_u32(sBl) + sdst;
  constexpr uint32_t RSTEP = 64 * LDAB * 2;

  const int KT = K / 32;

  auto load_tile = [&](int kt, int buf) {
    const size_t g = (size_t)kt * 32;
    const uint32_t so = (uint32_t)buf * GTILE_B;
    const size_t a2 = aoff + g, b2 = boff + g;
    cp_async16(sAh0 + so,         Ah + a2);
    cp_async16(sAh0 + so + RSTEP, Ah + a2 + (size_t)64 * K);
    cp_async16(sAl0 + so,         Al + a2);
    cp_async16(sAl0 + so + RSTEP, Al + a2 + (size_t)64 * K);
    cp_async16(sBh0 + so,         Bh + b2);
    cp_async16(sBh0 + so + RSTEP, Bh + b2 + (size_t)64 * K);
    cp_async16(sBl0 + so,         Bl + b2);
    cp_async16(sBl0 + so + RSTEP, Bl + b2 + (size_t)64 * K);
  };

  load_tile(0, 0);
  cp_commit();

  float acc[4][4][4];
#pragma unroll
  for (int i = 0; i < 4; ++i)
#pragma unroll
    for (int j = 0; j < 4; ++j)
#pragma unroll
      for (int r = 0; r < 4; ++r) acc[i][j][r] = 0.f;

  const int arow = wm * 64 + (lane & 15);
  const int acolx = ((lane >> 4) << 3);
  const int brow = wn * 32 + ((lane >> 4) << 3) + (lane & 7);
  const int bcolx = (((lane >> 3) & 1) << 3);
  const uint32_t sAhB = smem_u32(sAh), sAlB = smem_u32(sAl);
  const uint32_t sBhB = smem_u32(sBh), sBlB = smem_u32(sBl);

  for (int kt = 0; kt < KT; ++kt) {
    const int buf = kt & 1;
    cp_wait0();
    __syncthreads();
    if (kt + 1 < KT) {
      load_tile(kt + 1, buf ^ 1);
      cp_commit();
    }

    const uint32_t so = (uint32_t)buf * GTILE_B;
#pragma unroll
    for (int k2 = 0; k2 < 2; ++k2) {
      uint32_t afh[4][4], afl[4][4], bfh[4][2], bfl[4][2];
      const uint32_t acol = k2 * 16 + acolx;
      const uint32_t bcol = k2 * 16 + bcolx;
#pragma unroll
      for (int mt = 0; mt < 4; ++mt) {
        const uint32_t ao = so + (uint32_t)(((arow + mt * 16) * LDAB + acol) * 2);
        ldmx4(afh[mt], sAhB + ao);
        ldmx4(afl[mt], sAlB + ao);
      }
#pragma unroll
      for (int nt2 = 0; nt2 < 2; ++nt2) {
        uint32_t t[4];
        const uint32_t bo = so + (uint32_t)(((brow + nt2 * 16) * LDAB + bcol) * 2);
        ldmx4(t, sBhB + bo);
        bfh[nt2 * 2][0] = t[0]; bfh[nt2 * 2][1] = t[1];
        bfh[nt2 * 2 + 1][0] = t[2]; bfh[nt2 * 2 + 1][1] = t[3];
        ldmx4(t, sBlB + bo);
        bfl[nt2 * 2][0] = t[0]; bfl[nt2 * 2][1] = t[1];
        bfl[nt2 * 2 + 1][0] = t[2]; bfl[nt2 * 2 + 1][1] = t[3];
      }
#pragma unroll
      for (int mt = 0; mt < 4; ++mt)
#pragma unroll
        for (int nt = 0; nt < 4; ++nt) {
          mma_bf16(acc[mt][nt], afh[mt], bfh[nt][0], bfh[nt][1]);
          mma_bf16(acc[mt][nt], afh[mt], bfl[nt][0], bfl[nt][1]);
          mma_bf16(acc[mt][nt], afl[mt], bfh[nt][0], bfh[nt][1]);
        }
    }
  }

  float2 bv[4];
#pragma unroll
  for (int nt = 0; nt < 4; ++nt) {
    const int col = n0 + wn * 32 + nt * 8 + (lane & 3) * 2;
    if (HAS_BIAS) { bv[nt].x = bias[col]; bv[nt].y = bias[col + 1]; }
    else          { bv[nt].x = 0.f;       bv[nt].y = 0.f; }
  }
#pragma unroll
  for (int mt = 0; mt < 4; ++mt) {
    const int r0 = m0 + wm * 64 + mt * 16 + (lane >> 2);
#pragma unroll
    for (int nt = 0; nt < 4; ++nt) {
      const int col = n0 + wn * 32 + nt * 8 + (lane & 3) * 2;
      float2 v0 = make_float2(acc[mt][nt][0] + bv[nt].x, acc[mt][nt][1] + bv[nt].y);
      float2 v1 = make_float2(acc[mt][nt][2] + bv[nt].x, acc[mt][nt][3] + bv[nt].y);
      *(float2*)(C + (size_t)r0 * N + col) = v0;
      *(float2*)(C + (size_t)(r0 + 8) * N + col) = v1;
    }
  }
}

// ---------------------------------------------------------------------------
// Flash attention (R13 proven): bf16x3 MMA, 64x64 tiles, occ 2,
// V reuses K smem tiles.
// ---------------------------------------------------------------------------
constexpr int LDK = 136;
constexpr int LDP = 72;
constexpr int TILE_E = 64 * LDK;
constexpr int SM_QH = 0;
constexpr int SM_QL = TILE_E;
constexpr int SM_K1 = 2 * TILE_E;
constexpr int SM_K2 = 3 * TILE_E;
constexpr int SM_PH = 4 * TILE_E;
constexpr int SM_PL = 4 * TILE_E + 64 * LDP;
constexpr int SM_RED = 4 * TILE_E + 2 * 64 * LDP;
constexpr int FLASH4_SMEM = SM_RED * 2 + 2 * 128 * 4;

__global__ void __launch_bounds__(256, 2)
flash_mma(const __nv_bfloat16* __restrict__ Qh, const __nv_bfloat16* __restrict__ Ql,
          const __nv_bfloat16* __restrict__ Kh, const __nv_bfloat16* __restrict__ Kl,
          const __nv_bfloat16* __restrict__ Vh, const __nv_bfloat16* __restrict__ Vl,
          __nv_bfloat16* __restrict__ Oh, __nv_bfloat16* __restrict__ Ol, int Lr) {
  extern __shared__ __nv_bfloat16 sb[];
  const uint32_t sbase = smem_u32(sb);
  float* redm = (float*)(sb + SM_RED);
  float* reds = redm + 128;

  const int qt = blockIdx.x, h = blockIdx.y, b = blockIdx.z;
  const int kvh = h >> 3;
  const int q0 = qt * 64;
  const int tid = threadIdx.x, lane = tid & 31, w = tid >> 5;
  const int wm = w & 3, wn = w >> 2;

  const int lr = tid & 63, lcg = tid >> 6;
  const uint32_t sd = (uint32_t)((lr * LDK + lcg * 32) * 2);

  {
    const size_t grow = (size_t)(b * Lr + q0 + lr) * HID_C + h * D_C + lcg * 32;
#pragma unroll
    for (int i = 0; i < 4; ++i) {
      cp_async16(sbase + SM_QH * 2 + sd + i * 16, Qh + grow + i * 8);
      cp_async16(sbase + SM_QL * 2 + sd + i * 16, Ql + grow + i * 8);
    }
    cp_commit();
  }

  const int rq = lane >> 2, tq = lane & 3;
  const int arow = wm * 16 + (lane & 15);
  const int kcol8 = (lane >> 4) << 3;
  const int brow = wn * 32 + kcol8 + (lane & 7);
  const int bcol8 = ((lane >> 3) & 1) << 3;
  const int vrow = lane & 15;
  const int row0 = wm * 16 + rq;

  float m0 = -1e30f, m1 = -1e30f, l0 = 0.f, l1 = 0.f;
  float oacc[8][4];
#pragma unroll
  for (int i = 0; i < 8; ++i)
#pragma unroll
    for (int j = 0; j < 4; ++j) oacc[i][j] = 0.f;

  const float scale = 0.08838834764831845f;
  const uint32_t K1B = sbase + SM_K1 * 2;
  const uint32_t K2B = sbase + SM_K2 * 2;

  for (int kt = 0; kt <= qt; ++kt) {
    const int k0 = kt * 64;
    const size_t gr = (size_t)(b * Lr + k0 + lr) * NKVC + kvh * D_C + lcg * 32;

    __syncthreads();
#pragma unroll
    for (int i = 0; i < 4; ++i) {
      cp_async16(K1B + sd + i * 16, Kh + gr + i * 8);
      cp_async16(K2B + sd + i * 16, Kl + gr + i * 8);
    }
    cp_commit();
    cp_wait0();
    __syncthreads();

    float sa[4][4];
#pragma unroll
    for (int i = 0; i < 4; ++i)
#pragma unroll
      for (int j = 0; j < 4; ++j) sa[i][j] = 0.f;

#pragma unroll
    for (int kst = 0; kst < 8; ++kst) {
      uint32_t ah4[4], al4[4];
      const uint32_t ao = (uint32_t)((arow * LDK + kst * 16 + kcol8) * 2);
      ldmx4(ah4, sbase + SM_QH * 2 + ao);
      ldmx4(al4, sbase + SM_QL * 2 + ao);
      uint32_t bh[4][2], bl[4][2];
#pragma unroll
      for (int nt2 = 0; nt2 < 2; ++nt2) {
        uint32_t t4[4];
        const uint32_t bo = (uint32_t)(((brow + nt2 * 16) * LDK + kst * 16 + bcol8) * 2);
        ldmx4(t4, K1B + bo);
        bh[nt2 * 2][0] = t4[0]; bh[nt2 * 2][1] = t4[1];
        bh[nt2 * 2 + 1][0] = t4[2]; bh[nt2 * 2 + 1][1] = t4[3];
        ldmx4(t4, K2B + bo);
        bl[nt2 * 2][0] = t4[0]; bl[nt2 * 2][1] = t4[1];
        bl[nt2 * 2 + 1][0] = t4[2]; bl[nt2 * 2 + 1][1] = t4[3];
      }
#pragma unroll
      for (int nf = 0; nf < 4; ++nf) {
        mma_bf16(sa[nf], ah4, bh[nf][0], bh[nf][1]);
        mma_bf16(sa[nf], ah4, bl[nf][0], bl[nf][1]);
        mma_bf16(sa[nf], al4, bh[nf][0], bh[nf][1]);
      }
    }

    const bool diag = (kt == qt);
    float tmx0 = -1e30f, tmx1 = -1e30f;
#pragma unroll
    for (int nf = 0; nf < 4; ++nf) {
#pragma unroll
      for (int j = 0; j < 4; ++j) {
        float sv = sa[nf][j] * scale;
        if (diag) {
          const int col = wn * 32 + nf * 8 + 2 * tq + (j & 1);
          const int rowl = row0 + ((j >= 2) ? 8 : 0);
          if (col > rowl) sv = -1e30f;
        }
        sa[nf][j] = sv;
        if (j < 2) tmx0 = fmaxf(tmx0, sv); else tmx1 = fmaxf(tmx1, sv);
      }
    }
    tmx0 = fmaxf(tmx0, __shfl_xor_sync(0xffffffffu, tmx0, 1));
    tmx0 = fmaxf(tmx0, __shfl_xor_sync(0xffffffffu, tmx0, 2));
    tmx1 = fmaxf(tmx1, __shfl_xor_sync(0xffffffffu, tmx1, 1));
    tmx1 = fmaxf(tmx1, __shfl_xor_sync(0xffffffffu, tmx1, 2));
    if (tq == 0) {
      redm[wn * 64 + row0] = tmx0;
      redm[wn * 64 + row0 + 8] = tmx1;
    }
    __syncthreads();   // barrier A

#pragma unroll
    for (int i = 0; i < 4; ++i) {
      cp_async16(K1B + sd + i * 16, Vh + gr + i * 8);
      cp_async16(K2B + sd + i * 16, Vl + gr + i * 8);
    }
    cp_commit();

    const float fm0 = fmaxf(redm[row0], redm[64 + row0]);
    const float fm1 = fmaxf(redm[row0 + 8], redm[64 + row0 + 8]);
    const float mn0 = fmaxf(m0, fm0), mn1 = fmaxf(m1, fm1);
    const float al0 = __expf(m0 - mn0), al1 = __expf(m1 - mn1);
    m0 = mn0; m1 = mn1;

    float rs0 = 0.f, rs1 = 0.f;
#pragma unroll
    for (int nf = 0; nf < 4; ++nf) {
      float p0 = __expf(sa[nf][0] - mn0);
      float p1 = __expf(sa[nf][1] - mn0);
      float p2 = __expf(sa[nf][2] - mn1);
      float p3 = __expf(sa[nf][3] - mn1);
      rs0 += p0 + p1; rs1 += p2 + p3;
      sa[nf][0] = p0; sa[nf][1] = p1; sa[nf][2] = p2; sa[nf][3] = p3;
    }
    rs0 += __shfl_xor_sync(0xffffffffu, rs0, 1);
    rs0 += __shfl_xor_sync(0xffffffffu, rs0, 2);
    rs1 += __shfl_xor_sync(0xffffffffu, rs1, 1);
    rs1 += __shfl_xor_sync(0xffffffffu, rs1, 2);
    if (tq == 0) {
      reds[wn * 64 + row0] = rs0;
      reds[wn * 64 + row0 + 8] = rs1;
    }

#pragma unroll
    for (int nf = 0; nf < 8; ++nf) {
      oacc[nf][0] *= al0; oacc[nf][1] *= al0;
      oacc[nf][2] *= al1; oacc[nf][3] *= al1;
    }

#pragma unroll
    for (int nf = 0; nf < 4; ++nf) {
      const int pcol = wn * 32 + nf * 8 + 2 * tq;
      __nv_bfloat16 h0 = __float2bfloat16(sa[nf][0]);
      __nv_bfloat16 h1 = __float2bfloat16(sa[nf][1]);
      __nv_bfloat16 h2 = __float2bfloat16(sa[nf][2]);
      __nv_bfloat16 h3 = __float2bfloat16(sa[nf][3]);
      __nv_bfloat162 ph01; ph01.x = h0; ph01.y = h1;
      __nv_bfloat162 ph23; ph23.x = h2; ph23.y = h3;
      __nv_bfloat162 pl01, pl23;
      pl01.x = __float2bfloat16(sa[nf][0] - __bfloat162float(h0));
      pl01.y = __float2bfloat16(sa[nf][1] - __bfloat162float(h1));
      pl23.x = __float2bfloat16(sa[nf][2] - __bfloat162float(h2));
      pl23.y = __float2bfloat16(sa[nf][3] - __bfloat162float(h3));
      *(__nv_bfloat162*)(sb + SM_PH + row0 * LDP + pcol) = ph01;
      *(__nv_bfloat162*)(sb + SM_PH + (row0 + 8) * LDP + pcol) = ph23;
      *(__nv_bfloat162*)(sb + SM_PL + row0 * LDP + pcol) = pl01;
      *(__nv_bfloat162*)(sb + SM_PL + (row0 + 8) * LDP + pcol) = pl23;
    }
    cp_wait0();
    __syncthreads();   // barrier B

    l0 = l0 * al0 + (reds[row0] + reds[64 + row0]);
    l1 = l1 * al1 + (reds[row0 + 8] + reds[64 + row0 + 8]);

#pragma unroll
    for (int k0i = 0; k0i < 64; k0i += 16) {
      uint32_t pah[4], pal[4];
      const uint32_t po = (uint32_t)((arow * LDP + k0i + kcol8) * 2);
      ldmx4(pah, sbase + SM_PH * 2 + po);
      ldmx4(pal, sbase + SM_PL * 2 + po);
#pragma unroll
      for (int df = 0; df < 4; ++df) {
        uint32_t th[4], tl[4];
        const uint32_t bo = (uint32_t)(((k0i + vrow) * LDK + wn * 64 + df * 16 + kcol8) * 2);
        ldmx4t(th, K1B + bo);
        ldmx4t(tl, K2B + bo);
        mma_bf16(oacc[df * 2],     pah, th[0], th[1]);
        mma_bf16(oacc[df * 2],     pah, tl[0], tl[1]);
        mma_bf16(oacc[df * 2],     pal, th[0], th[1]);
        mma_bf16(oacc[df * 2 + 1], pah, th[2], th[3]);
        mma_bf16(oacc[df * 2 + 1], pah, tl[2], tl[3]);
        mma_bf16(oacc[df * 2 + 1], pal, th[2], th[3]);
      }
    }
  }

  const float inv0 = 1.f / l0, inv1 = 1.f / l1;
  const size_t gr0 = (size_t)(b * Lr + q0 + row0) * HID_C;
  const size_t gr1 = gr0 + (size_t)8 * HID_C;
#pragma unroll
  for (int nf = 0; nf < 8; ++nf) {
    const int col = h * D_C + wn * 64 + nf * 8 + 2 * tq;
    float o0 = oacc[nf][0] * inv0, o1 = oacc[nf][1] * inv0;
    float o2 = oacc[nf][2] * inv1, o3 = oacc[nf][3] * inv1;
    __nv_bfloat162 h01, h23, l01, l23;
    h01.x = __float2bfloat16(o0); h01.y = __float2bfloat16(o1);
    h23.x = __float2bfloat16(o2); h23.y = __float2bfloat16(o3);
    l01.x = __float2bfloat16(o0 - __bfloat162float(h01.x));
    l01.y = __float2bfloat16(o1 - __bfloat162float(h01.y));
    l23.x = __float2bfloat16(o2 - __bfloat162float(h23.x));
    l23.y = __float2bfloat16(o3 - __bfloat162float(h23.y));
    *(__nv_bfloat162*)(Oh + gr0 + col) = h01;
    *(__nv_bfloat162*)(Oh + gr1 + col) = h23;
    *(__nv_bfloat162*)(Ol + gr0 + col) = l01;
    *(__nv_bfloat162*)(Ol + gr1 + col) = l23;
  }
}

// ---------------------------------------------------------------------------
// kernel_launch: x, cos, sin, wq, bq, wk, bk, wv, bv, wo
// ---------------------------------------------------------------------------
extern "C" void kernel_launch(void* const* d_in, const int* in_sizes, int n_in,
                              void* d_out, int out_size) {
  const float* x  = (const float*)d_in[0];
  const float* cs = (const float*)d_in[1];
  const float* sn = (const float*)d_in[2];
  const float* wq = (const float*)d_in[3];
  const float* bq = (const float*)d_in[4];
  const float* wk = (const float*)d_in[5];
  const float* bk = (const float*)d_in[6];
  const float* wv = (const float*)d_in[7];
  const float* bv = (const float*)d_in[8];
  const float* wo = (const float*)d_in[9];
  float* out = (float*)d_out;

  const int Lr = in_sizes[1] / 128;
  const int Mr = in_sizes[0] / HID_C;

  void *qkvp, *bcp;
  void *xh, *xl, *wch, *wcl, *woh, *wol, *ah, *al;
  void *qhp, *qlp, *khp, *klp, *vhp, *vlp;
  cudaGetSymbolAddress(&qkvp, g_qkv);  cudaGetSymbolAddress(&bcp, g_bcat);
  cudaGetSymbolAddress(&xh, g_xh);     cudaGetSymbolAddress(&xl, g_xl);
  cudaGetSymbolAddress(&wch, g_wcath); cudaGetSymbolAddress(&wcl, g_wcatl);
  cudaGetSymbolAddress(&woh, g_woh);   cudaGetSymbolAddress(&wol, g_wol);
  cudaGetSymbolAddress(&ah, g_ah);     cudaGetSymbolAddress(&al, g_al);
  cudaGetSymbolAddress(&qhp, g_qh);    cudaGetSymbolAddress(&qlp, g_ql);
  cudaGetSymbolAddress(&khp, g_kh);    cudaGetSymbolAddress(&klp, g_kl);
  cudaGetSymbolAddress(&vhp, g_vh);    cudaGetSymbolAddress(&vlp, g_vl);

  cudaFuncSetAttribute(gemm_bf16x3<true>,  cudaFuncAttributeMaxDynamicSharedMemorySize, GEMM_SMEM);
  cudaFuncSetAttribute(gemm_bf16x3<false>, cudaFuncAttributeMaxDynamicSharedMemorySize, GEMM_SMEM);
  cudaFuncSetAttribute(flash_mma,          cudaFuncAttributeMaxDynamicSharedMemorySize, FLASH4_SMEM);

  dim3 blk(256);

  // 1) fused prep: all input splits + bias concat (one launch)
  const int n_x4 = Mr * HID_C / 4;
  const int prep_total = n_x4 + (HID_C * HID_C / 4) + 2 * (NKVC * HID_C / 4)
                       + (HID_C * HID_C / 4) + (NCAT / 4);
  prep_all<<<(prep_total + 255) / 256, blk>>>(
      x, wq, wk, wv, wo, bq, bk, bv,
      (__nv_bfloat16*)xh, (__nv_bfloat16*)xl,
      (__nv_bfloat16*)wch, (__nv_bfloat16*)wcl,
      (__nv_bfloat16*)woh, (__nv_bfloat16*)wol,
      (float*)bcp, n_x4);

  // 2) fused QKV projection (N=2560)
  dim3 gqkv(NCAT / 128, Mr / 128);
  gemm_bf16x3<true><<<gqkv, blk, GEMM_SMEM>>>(
      (const __nv_bfloat16*)xh, (const __nv_bfloat16*)xl,
      (const __nv_bfloat16*)wch, (const __nv_bfloat16*)wcl,
      (const float*)bcp, (float*)qkvp, Mr, NCAT, HID_C);

  // 3) fused RoPE(q,k) + split(v) (one launch)
  const int rt = Mr * (H_C + 2 * KV_C) * 64;
  rope_split_v<<<(rt + 255) / 256, blk>>>(
      (const float*)qkvp, cs, sn,
      (__nv_bfloat16*)qhp, (__nv_bfloat16*)qlp,
      (__nv_bfloat16*)khp, (__nv_bfloat16*)klp,
      (__nv_bfloat16*)vhp, (__nv_bfloat16*)vlp, Lr, Mr);

  // 4) flash attention (writes bf16 hi/lo output)
  dim3 gf(Lr / 64, H_C, Mr / Lr);
  flash_mma<<<gf, blk, FLASH4_SMEM>>>(
      (const __nv_bfloat16*)qhp, (const __nv_bfloat16*)qlp,
      (const __nv_bfloat16*)khp, (const __nv_bfloat16*)klp,
      (const __nv_bfloat16*)vhp, (const __nv_bfloat16*)vlp,
      (__nv_bfloat16*)ah, (__nv_bfloat16*)al, Lr);

  // 5) output projection
  dim3 go(HID_C / 128, Mr / 128);
  gemm_bf16x3<false><<<go, blk, GEMM_SMEM>>>(
      (const __nv_bfloat16*)ah, (const __nv_bfloat16*)al,
      (const __nv_bfloat16*)woh, (const __nv_bfloat16*)wol,
      nullptr, out, Mr, HID_C, HID_C);
}